// round 7
// baseline (speedup 1.0000x reference)
#include <cuda_runtime.h>
#include <math.h>
#include <stdint.h>

#define NA   4096
#define NE   131072
#define TPIN 1152
#define SPLIT 2

typedef unsigned long long u64t;

__device__ __forceinline__ u64t pk2(float a, float b) {
    u64t r; asm("mov.b64 %0,{%1,%2};" : "=l"(r) : "f"(a), "f"(b)); return r;
}
__device__ __forceinline__ void upk2(u64t v, float& a, float& b) {
    asm("mov.b64 {%0,%1},%2;" : "=f"(a), "=f"(b) : "l"(v));
}
__device__ __forceinline__ u64t ffma2(u64t a, u64t b, u64t c) {
    u64t d; asm("fma.rn.f32x2 %0,%1,%2,%3;" : "=l"(d) : "l"(a), "l"(b), "l"(c)); return d;
}
__device__ __forceinline__ uint32_t tf32r(float f) {
    uint32_t u; asm("cvt.rna.tf32.f32 %0,%1;" : "=r"(u) : "f"(f)); return u;
}
__device__ __forceinline__ void mma_tf32(float* c, const uint32_t* a, uint32_t b0, uint32_t b1) {
    asm volatile("mma.sync.aligned.m16n8k8.row.col.f32.tf32.tf32.f32 "
        "{%0,%1,%2,%3},{%4,%5,%6,%7},{%8,%9},{%0,%1,%2,%3};"
        : "+f"(c[0]), "+f"(c[1]), "+f"(c[2]), "+f"(c[3])
        : "r"(a[0]), "r"(a[1]), "r"(a[2]), "r"(a[3]), "r"(b0), "r"(b1));
}

// ---------------- scratch ----------------
__device__ float g_sh[NE * 9];
__device__ float g_rad[(size_t)NE * 128];
__device__ int   g_hist[NA];
__device__ int   g_off[NA];
__device__ int   g_cur[NA];
__device__ int   g_elist[NE];
__device__ float g_A[(size_t)NA * TPIN];
__device__ float g_comb[NA * 128];
__device__ float g_hid[NA * 128];
__device__ float g_upd[NA * 128];
__device__ float g_qkv[NA * 384];
__device__ float g_att[NA * 128];
__device__ float g_t1[NA * 128];
__device__ float g_t2[NA * 128];
__device__ float g_mix[NA * 128];
__device__ float g_pO[(size_t)SPLIT * NA * 128];
__device__ float g_pml[(size_t)SPLIT * NA * 4 * 2];

// ---------------- fused edge kernel ----------------
__global__ __launch_bounds__(256) void edge_fused_kernel(
        const float* __restrict__ ev, const float* __restrict__ el,
        const float* __restrict__ W1, const float* __restrict__ b1,
        const float* __restrict__ W2, const float* __restrict__ b2) {
    __shared__ float sW1[8 * 64];
    __shared__ float sb1[64];
    __shared__ __align__(16) float sW2[64 * 128];
    __shared__ float sb2[128];
    for (int i = threadIdx.x; i < 512;  i += 256) sW1[i] = W1[i];
    for (int i = threadIdx.x; i < 64;   i += 256) sb1[i] = b1[i];
    for (int i = threadIdx.x; i < 8192; i += 256) sW2[i] = W2[i];
    for (int i = threadIdx.x; i < 128;  i += 256) sb2[i] = b2[i];
    __syncthreads();

    int warp = threadIdx.x >> 5, lane = threadIdx.x & 31;
    const float PIC = 3.14159265358979323846f / 6.0f;
    for (int it = 0; it < NE / 4096; it++) {
        int e = blockIdx.x * 8 + warp + it * 4096;
        float vx = ev[e * 3 + 0], vy = ev[e * 3 + 1], vz = ev[e * 3 + 2];
        float l = el[e];
        float r = sqrtf(vx * vx + vy * vy + vz * vz) + 1e-8f;
        float x = vx / r, y = vy / r, z = vz / r;
        if (lane < 9) {
            float s;
            switch (lane) {
                case 0: s = 1.f; break;
                case 1: s = y; break;
                case 2: s = z; break;
                case 3: s = x; break;
                case 4: s = 3.f * z * z - 1.f; break;
                case 5: s = x * z; break;
                case 6: s = y * z; break;
                case 7: s = x * y; break;
                default: s = x * x - y * y; break;
            }
            g_sh[e * 9 + lane] = s;
        }
        float env = 0.5f * (__cosf(l * PIC) + 1.f) * (l < 6.0f ? 1.f : 0.f);
        float inv_l_env = env / l;
        float rb[8];
#pragma unroll
        for (int b = 0; b < 8; b++) rb[b] = __sinf(l * (float)(b + 1) * PIC) * inv_l_env;
        float h1a = sb1[lane], h1b = sb1[lane + 32];
#pragma unroll
        for (int b = 0; b < 8; b++) {
            h1a += rb[b] * sW1[b * 64 + lane];
            h1b += rb[b] * sW1[b * 64 + lane + 32];
        }
        h1a = h1a / (1.f + __expf(-h1a));
        h1b = h1b / (1.f + __expf(-h1b));
        u64t acc0 = pk2(sb2[lane * 4 + 0], sb2[lane * 4 + 1]);
        u64t acc1 = pk2(sb2[lane * 4 + 2], sb2[lane * 4 + 3]);
#pragma unroll
        for (int k = 0; k < 64; k++) {
            float hk = (k < 32) ? __shfl_sync(0xffffffffu, h1a, k)
                                : __shfl_sync(0xffffffffu, h1b, k - 32);
            u64t hk2 = pk2(hk, hk);
            ulonglong2 w = *(const ulonglong2*)&sW2[k * 128 + lane * 4];
            acc0 = ffma2(hk2, w.x, acc0);
            acc1 = ffma2(hk2, w.y, acc1);
        }
        float o0, o1, o2, o3;
        upk2(acc0, o0, o1); upk2(acc1, o2, o3);
        o0 = o0 / (1.f + __expf(-o0));
        o1 = o1 / (1.f + __expf(-o1));
        o2 = o2 / (1.f + __expf(-o2));
        o3 = o3 / (1.f + __expf(-o3));
        *(float4*)&g_rad[(size_t)e * 128 + lane * 4] = make_float4(o0, o1, o2, o3);
    }
}

// ---------------- tf32 tensor-core GEMM: C = act(A @ W + bias) -------------
// BM=64, BN=64, BK=32, 128 threads (4 warps); warp = 16 rows.
// As stride 36 (bank (4g+tg)), Bs stride 68 (bank (4tg+g)) — conflict-free.
#define AS_STR 36
#define BS_STR 68
__global__ __launch_bounds__(128) void gemm_tf32_kernel(
        const float* __restrict__ A, const float* __restrict__ W,
        const float* __restrict__ bias, float* __restrict__ C,
        int M, int N, int K, int ldw, int act) {
    __shared__ float As[64 * AS_STR];
    __shared__ float Bs[32 * BS_STR];
    int tid = threadIdx.x, lane = tid & 31, w = tid >> 5;
    int g = lane >> 2, tg = lane & 3;
    int m0 = blockIdx.x * 64, n0 = blockIdx.y * 64;
    float Cacc[8][4] = {};
    for (int k0 = 0; k0 < K; k0 += 32) {
#pragma unroll
        for (int i = 0; i < 4; i++) {
            int idx = tid + i * 128;
            int r = idx >> 3, c = (idx & 7) * 4;
            float4 v = *(const float4*)&A[(size_t)(m0 + r) * K + k0 + c];
            As[r * AS_STR + c + 0] = __uint_as_float(tf32r(v.x));
            As[r * AS_STR + c + 1] = __uint_as_float(tf32r(v.y));
            As[r * AS_STR + c + 2] = __uint_as_float(tf32r(v.z));
            As[r * AS_STR + c + 3] = __uint_as_float(tf32r(v.w));
        }
#pragma unroll
        for (int i = 0; i < 4; i++) {
            int idx = tid + i * 128;
            int k = idx >> 4, n = (idx & 15) * 4;
            float4 v = *(const float4*)&W[(size_t)(k0 + k) * ldw + n0 + n];
            Bs[k * BS_STR + n + 0] = __uint_as_float(tf32r(v.x));
            Bs[k * BS_STR + n + 1] = __uint_as_float(tf32r(v.y));
            Bs[k * BS_STR + n + 2] = __uint_as_float(tf32r(v.z));
            Bs[k * BS_STR + n + 3] = __uint_as_float(tf32r(v.w));
        }
        __syncthreads();
        int mrow = w * 16;
#pragma unroll
        for (int kt = 0; kt < 4; kt++) {
            uint32_t a[4];
            a[0] = __float_as_uint(As[(mrow + g) * AS_STR + kt * 8 + tg]);
            a[1] = __float_as_uint(As[(mrow + g + 8) * AS_STR + kt * 8 + tg]);
            a[2] = __float_as_uint(As[(mrow + g) * AS_STR + kt * 8 + tg + 4]);
            a[3] = __float_as_uint(As[(mrow + g + 8) * AS_STR + kt * 8 + tg + 4]);
#pragma unroll
            for (int nt = 0; nt < 8; nt++) {
                uint32_t b0 = __float_as_uint(Bs[(kt * 8 + tg) * BS_STR + nt * 8 + g]);
                uint32_t b1 = __float_as_uint(Bs[(kt * 8 + tg + 4) * BS_STR + nt * 8 + g]);
                mma_tf32(Cacc[nt], a, b0, b1);
            }
        }
        __syncthreads();
    }
    int row0 = m0 + w * 16 + g, row1 = row0 + 8;
#pragma unroll
    for (int nt = 0; nt < 8; nt++) {
        int col = n0 + nt * 8 + 2 * tg;
        float b0v = bias[col], b1v = bias[col + 1];
        float v00 = Cacc[nt][0] + b0v, v01 = Cacc[nt][1] + b1v;
        float v10 = Cacc[nt][2] + b0v, v11 = Cacc[nt][3] + b1v;
        if (act == 1) {
            v00 = v00 / (1.f + __expf(-v00)); v01 = v01 / (1.f + __expf(-v01));
            v10 = v10 / (1.f + __expf(-v10)); v11 = v11 / (1.f + __expf(-v11));
        } else if (act == 2) {
            v00 = 1.f / (1.f + __expf(-v00)); v01 = 1.f / (1.f + __expf(-v01));
            v10 = 1.f / (1.f + __expf(-v10)); v11 = 1.f / (1.f + __expf(-v11));
        }
        C[(size_t)row0 * N + col] = v00; C[(size_t)row0 * N + col + 1] = v01;
        C[(size_t)row1 * N + col] = v10; C[(size_t)row1 * N + col + 1] = v11;
    }
}

// ---------------- tf32 split-K agg GEMM: g_A @ W_tp[:, :64] -> atomic ------
__global__ __launch_bounds__(128) void agg_gemm_mma(const float* __restrict__ Wtp) {
    __shared__ float As[64 * AS_STR];
    __shared__ float Bs[32 * BS_STR];
    int tid = threadIdx.x, lane = tid & 31, w = tid >> 5;
    int g = lane >> 2, tg = lane & 3;
    int m0 = blockIdx.x * 64;
    int kb = blockIdx.y * 288;
    float Cacc[8][4] = {};
    for (int k0 = kb; k0 < kb + 288; k0 += 32) {
#pragma unroll
        for (int i = 0; i < 4; i++) {
            int idx = tid + i * 128;
            int r = idx >> 3, c = (idx & 7) * 4;
            float4 v = *(const float4*)&g_A[(size_t)(m0 + r) * TPIN + k0 + c];
            As[r * AS_STR + c + 0] = __uint_as_float(tf32r(v.x));
            As[r * AS_STR + c + 1] = __uint_as_float(tf32r(v.y));
            As[r * AS_STR + c + 2] = __uint_as_float(tf32r(v.z));
            As[r * AS_STR + c + 3] = __uint_as_float(tf32r(v.w));
        }
#pragma unroll
        for (int i = 0; i < 4; i++) {
            int idx = tid + i * 128;
            int k = idx >> 4, n = (idx & 15) * 4;
            float4 v = *(const float4*)&Wtp[(size_t)(k0 + k) * 128 + n];
            Bs[k * BS_STR + n + 0] = __uint_as_float(tf32r(v.x));
            Bs[k * BS_STR + n + 1] = __uint_as_float(tf32r(v.y));
            Bs[k * BS_STR + n + 2] = __uint_as_float(tf32r(v.z));
            Bs[k * BS_STR + n + 3] = __uint_as_float(tf32r(v.w));
        }
        __syncthreads();
        int mrow = w * 16;
#pragma unroll
        for (int kt = 0; kt < 4; kt++) {
            uint32_t a[4];
            a[0] = __float_as_uint(As[(mrow + g) * AS_STR + kt * 8 + tg]);
            a[1] = __float_as_uint(As[(mrow + g + 8) * AS_STR + kt * 8 + tg]);
            a[2] = __float_as_uint(As[(mrow + g) * AS_STR + kt * 8 + tg + 4]);
            a[3] = __float_as_uint(As[(mrow + g + 8) * AS_STR + kt * 8 + tg + 4]);
#pragma unroll
            for (int nt = 0; nt < 8; nt++) {
                uint32_t b0 = __float_as_uint(Bs[(kt * 8 + tg) * BS_STR + nt * 8 + g]);
                uint32_t b1 = __float_as_uint(Bs[(kt * 8 + tg + 4) * BS_STR + nt * 8 + g]);
                mma_tf32(Cacc[nt], a, b0, b1);
            }
        }
        __syncthreads();
    }
    int row0 = m0 + w * 16 + g, row1 = row0 + 8;
#pragma unroll
    for (int nt = 0; nt < 8; nt++) {
        int col = 64 + nt * 8 + 2 * tg;
        atomicAdd(&g_comb[row0 * 128 + col],     Cacc[nt][0]);
        atomicAdd(&g_comb[row0 * 128 + col + 1], Cacc[nt][1]);
        atomicAdd(&g_comb[row1 * 128 + col],     Cacc[nt][2]);
        atomicAdd(&g_comb[row1 * 128 + col + 1], Cacc[nt][3]);
    }
}

// ---------------- CSR build ----------------
__global__ void zero_hist_kernel() {
    int i = blockIdx.x * blockDim.x + threadIdx.x;
    if (i < NA) g_hist[i] = 0;
}
__global__ void hist_kernel(const int* __restrict__ ei) {
    for (int e = blockIdx.x * blockDim.x + threadIdx.x; e < NE; e += gridDim.x * blockDim.x)
        atomicAdd(&g_hist[ei[NE + e]], 1);
}
__global__ void scan_kernel() {
    __shared__ int s[1024];
    int t = threadIdx.x;
    int v0 = g_hist[t * 4], v1 = g_hist[t * 4 + 1], v2 = g_hist[t * 4 + 2], v3 = g_hist[t * 4 + 3];
    int sum = v0 + v1 + v2 + v3;
    s[t] = sum;
    __syncthreads();
    for (int d = 1; d < 1024; d <<= 1) {
        int add = (t >= d) ? s[t - d] : 0;
        __syncthreads();
        s[t] += add;
        __syncthreads();
    }
    int base = s[t] - sum;
    g_off[t * 4 + 0] = base;                 g_cur[t * 4 + 0] = base;
    g_off[t * 4 + 1] = base + v0;            g_cur[t * 4 + 1] = base + v0;
    g_off[t * 4 + 2] = base + v0 + v1;       g_cur[t * 4 + 2] = base + v0 + v1;
    g_off[t * 4 + 3] = base + v0 + v1 + v2;  g_cur[t * 4 + 3] = base + v0 + v1 + v2;
}
__global__ void scatter_kernel(const int* __restrict__ ei) {
    for (int e = blockIdx.x * blockDim.x + threadIdx.x; e < NE; e += gridDim.x * blockDim.x) {
        int d = ei[NE + e];
        int p = atomicAdd(&g_cur[d], 1);
        g_elist[p] = e;
    }
}

// ---------------- per-node rank-1 aggregation ----------------
__global__ void aggregate_kernel() {
    int n = blockIdx.x;
    int c = threadIdx.x;  // 128
    int start = g_off[n], cnt = g_hist[n];
    __shared__ int   eid[32];
    __shared__ float shs[32 * 9];
    float acc[9] = {};
    for (int base = 0; base < cnt; base += 32) {
        int m = min(32, cnt - base);
        if (c < m) eid[c] = g_elist[start + base + c];
        __syncthreads();
        for (int j = c; j < m * 9; j += 128) shs[j] = g_sh[(size_t)eid[j / 9] * 9 + j % 9];
        __syncthreads();
        for (int i = 0; i < m; i++) {
            float rv = g_rad[(size_t)eid[i] * 128 + c];
#pragma unroll
            for (int s = 0; s < 9; s++) acc[s] += rv * shs[i * 9 + s];
        }
        __syncthreads();
    }
    size_t b = (size_t)n * TPIN;
    g_A[b + c] = acc[0];
#pragma unroll
    for (int s = 1; s < 4; s++) g_A[b + 128 + c * 3 + (s - 1)] = acc[s];
#pragma unroll
    for (int s = 4; s < 9; s++) g_A[b + 512 + c * 5 + (s - 4)] = acc[s];
}

// ---------------- embed + bias*deg init of g_comb ----------------
__global__ void embed_kernel(const int* __restrict__ an, const float* __restrict__ emb,
                             const float* __restrict__ btp) {
    int i = blockIdx.x * blockDim.x + threadIdx.x;
    if (i < NA * 128) {
        int n = i >> 7, j = i & 127;
        g_comb[i] = (j < 64) ? emb[an[n] * 64 + j]
                             : btp[j - 64] * (float)g_hist[n];
    }
}

// ---------------- tensor-core split-KV attention partials ----------------
#define KS_STR 44
#define VS_STR 40
#define PS_STR 76
__global__ __launch_bounds__(128) void attn_part_mma() {
    __shared__ float Ks[64 * KS_STR];
    __shared__ float Vs[64 * VS_STR];
    __shared__ float Ps[64 * PS_STR];
    int tid = threadIdx.x, lane = tid & 31, w = tid >> 5;
    int h = blockIdx.y, sp = blockIdx.z;
    int q0 = blockIdx.x * 64;
    int g = lane >> 2, tg = lane & 3;
    const float sc = 0.17677669529663687f;  // 1/sqrt(32)
    int r0 = q0 + w * 16 + g;

    uint32_t Qf[4][4];
#pragma unroll
    for (int kt = 0; kt < 4; kt++) {
        int k0 = kt * 8 + tg;
        Qf[kt][0] = tf32r(g_qkv[(size_t)r0 * 384 + h * 32 + k0] * sc);
        Qf[kt][1] = tf32r(g_qkv[(size_t)(r0 + 8) * 384 + h * 32 + k0] * sc);
        Qf[kt][2] = tf32r(g_qkv[(size_t)r0 * 384 + h * 32 + k0 + 4] * sc);
        Qf[kt][3] = tf32r(g_qkv[(size_t)(r0 + 8) * 384 + h * 32 + k0 + 4] * sc);
    }

    float O[4][4] = {};
    float M0 = -1e30f, M1 = -1e30f, L0 = 0.f, L1 = 0.f;

    for (int t0 = sp * (NA / SPLIT); t0 < (sp + 1) * (NA / SPLIT); t0 += 64) {
#pragma unroll
        for (int ii = 0; ii < 4; ii++) {
            int idx = tid + ii * 128;
            int key = idx >> 3, d = (idx & 7) * 4;
            float4 kv = *(const float4*)&g_qkv[(size_t)(t0 + key) * 384 + 128 + h * 32 + d];
            float4 vv = *(const float4*)&g_qkv[(size_t)(t0 + key) * 384 + 256 + h * 32 + d];
            float4 kc, vc;
            kc.x = __uint_as_float(tf32r(kv.x)); kc.y = __uint_as_float(tf32r(kv.y));
            kc.z = __uint_as_float(tf32r(kv.z)); kc.w = __uint_as_float(tf32r(kv.w));
            vc.x = __uint_as_float(tf32r(vv.x)); vc.y = __uint_as_float(tf32r(vv.y));
            vc.z = __uint_as_float(tf32r(vv.z)); vc.w = __uint_as_float(tf32r(vv.w));
            *(float4*)&Ks[key * KS_STR + d] = kc;
            *(float4*)&Vs[key * VS_STR + d] = vc;
        }
        __syncthreads();

        float S[8][4];
#pragma unroll
        for (int nt = 0; nt < 8; nt++) { S[nt][0] = 0.f; S[nt][1] = 0.f; S[nt][2] = 0.f; S[nt][3] = 0.f; }
#pragma unroll
        for (int nt = 0; nt < 8; nt++)
#pragma unroll
            for (int kt = 0; kt < 4; kt++) {
                uint32_t b0 = __float_as_uint(Ks[(nt * 8 + g) * KS_STR + kt * 8 + tg]);
                uint32_t b1 = __float_as_uint(Ks[(nt * 8 + g) * KS_STR + kt * 8 + tg + 4]);
                mma_tf32(S[nt], Qf[kt], b0, b1);
            }

        float rm0 = -1e30f, rm1 = -1e30f;
#pragma unroll
        for (int nt = 0; nt < 8; nt++) {
            rm0 = fmaxf(rm0, fmaxf(S[nt][0], S[nt][1]));
            rm1 = fmaxf(rm1, fmaxf(S[nt][2], S[nt][3]));
        }
        rm0 = fmaxf(rm0, __shfl_xor_sync(0xffffffffu, rm0, 1));
        rm0 = fmaxf(rm0, __shfl_xor_sync(0xffffffffu, rm0, 2));
        rm1 = fmaxf(rm1, __shfl_xor_sync(0xffffffffu, rm1, 1));
        rm1 = fmaxf(rm1, __shfl_xor_sync(0xffffffffu, rm1, 2));
        float Mn0 = fmaxf(M0, rm0), Mn1 = fmaxf(M1, rm1);
        float sc0 = __expf(M0 - Mn0), sc1 = __expf(M1 - Mn1);
        M0 = Mn0; M1 = Mn1;
        float ps0 = 0.f, ps1 = 0.f;
#pragma unroll
        for (int nt = 0; nt < 8; nt++) {
            S[nt][0] = __expf(S[nt][0] - Mn0); ps0 += S[nt][0];
            S[nt][1] = __expf(S[nt][1] - Mn0); ps0 += S[nt][1];
            S[nt][2] = __expf(S[nt][2] - Mn1); ps1 += S[nt][2];
            S[nt][3] = __expf(S[nt][3] - Mn1); ps1 += S[nt][3];
        }
        ps0 += __shfl_xor_sync(0xffffffffu, ps0, 1);
        ps0 += __shfl_xor_sync(0xffffffffu, ps0, 2);
        ps1 += __shfl_xor_sync(0xffffffffu, ps1, 1);
        ps1 += __shfl_xor_sync(0xffffffffu, ps1, 2);
        L0 = L0 * sc0 + ps0;
        L1 = L1 * sc1 + ps1;
#pragma unroll
        for (int nt2 = 0; nt2 < 4; nt2++) {
            O[nt2][0] *= sc0; O[nt2][1] *= sc0;
            O[nt2][2] *= sc1; O[nt2][3] *= sc1;
        }

        int pr = w * 16 + g;
#pragma unroll
        for (int nt = 0; nt < 8; nt++) {
            Ps[pr * PS_STR + nt * 8 + 2 * tg]           = __uint_as_float(tf32r(S[nt][0]));
            Ps[pr * PS_STR + nt * 8 + 2 * tg + 1]       = __uint_as_float(tf32r(S[nt][1]));
            Ps[(pr + 8) * PS_STR + nt * 8 + 2 * tg]     = __uint_as_float(tf32r(S[nt][2]));
            Ps[(pr + 8) * PS_STR + nt * 8 + 2 * tg + 1] = __uint_as_float(tf32r(S[nt][3]));
        }
        __syncwarp();

#pragma unroll
        for (int kt2 = 0; kt2 < 8; kt2++) {
            uint32_t A[4];
            A[0] = __float_as_uint(Ps[pr * PS_STR + kt2 * 8 + tg]);
            A[1] = __float_as_uint(Ps[(pr + 8) * PS_STR + kt2 * 8 + tg]);
            A[2] = __float_as_uint(Ps[pr * PS_STR + kt2 * 8 + tg + 4]);
            A[3] = __float_as_uint(Ps[(pr + 8) * PS_STR + kt2 * 8 + tg + 4]);
#pragma unroll
            for (int nt2 = 0; nt2 < 4; nt2++) {
                uint32_t b0 = __float_as_uint(Vs[(kt2 * 8 + tg) * VS_STR + nt2 * 8 + g]);
                uint32_t b1 = __float_as_uint(Vs[(kt2 * 8 + tg + 4) * VS_STR + nt2 * 8 + g]);
                mma_tf32(O[nt2], A, b0, b1);
            }
        }
        __syncthreads();
    }

    size_t base = (size_t)sp * NA;
#pragma unroll
    for (int nt2 = 0; nt2 < 4; nt2++) {
        int col = h * 32 + nt2 * 8 + 2 * tg;
        g_pO[(base + r0) * 128 + col]           = O[nt2][0];
        g_pO[(base + r0) * 128 + col + 1]       = O[nt2][1];
        g_pO[(base + r0 + 8) * 128 + col]       = O[nt2][2];
        g_pO[(base + r0 + 8) * 128 + col + 1]   = O[nt2][3];
    }
    if (tg == 0) {
        g_pml[((base + r0) * 4 + h) * 2 + 0]     = M0;
        g_pml[((base + r0) * 4 + h) * 2 + 1]     = L0;
        g_pml[((base + r0 + 8) * 4 + h) * 2 + 0] = M1;
        g_pml[((base + r0 + 8) * 4 + h) * 2 + 1] = L1;
    }
}

// ---------------- combine split-KV partials ----------------
__global__ void attn_combine_kernel() {
    int i = blockIdx.x * blockDim.x + threadIdx.x;
    if (i >= NA * 128) return;
    int qi = i >> 7, hd = i & 127, h = hd >> 5;
    float m[SPLIT], l[SPLIT];
    float M = -1e30f;
#pragma unroll
    for (int s = 0; s < SPLIT; s++) {
        size_t base = (size_t)s * NA + qi;
        m[s] = g_pml[(base * 4 + h) * 2 + 0];
        l[s] = g_pml[(base * 4 + h) * 2 + 1];
        M = fmaxf(M, m[s]);
    }
    float L = 0.f, O = 0.f;
#pragma unroll
    for (int s = 0; s < SPLIT; s++) {
        float w = __expf(m[s] - M);
        L += l[s] * w;
        O += g_pO[((size_t)s * NA + qi) * 128 + hd] * w;
    }
    g_att[i] = O / L;
}

// ---------------- mix: g_mix = g*t1 + (1-g)*upd ----------------
__global__ void mix_kernel() {
    int i = blockIdx.x * blockDim.x + threadIdx.x;
    if (i < NA * 128) {
        float gg = g_t2[i];
        g_mix[i] = gg * g_t1[i] + (1.f - gg) * g_upd[i];
    }
}

// ---------------- launch ----------------
extern "C" void kernel_launch(void* const* d_in, const int* in_sizes, int n_in,
                              void* d_out, int out_size) {
    const int*   an    = (const int*)d_in[0];
    const int*   ei    = (const int*)d_in[2];
    const float* ev    = (const float*)d_in[3];
    const float* el    = (const float*)d_in[4];
    const float* emb   = (const float*)d_in[5];
    const float* W_r1  = (const float*)d_in[6];  const float* b_r1 = (const float*)d_in[7];
    const float* W_r2  = (const float*)d_in[8];  const float* b_r2 = (const float*)d_in[9];
    const float* W_tp  = (const float*)d_in[10]; const float* b_tp = (const float*)d_in[11];
    const float* W_m1  = (const float*)d_in[12]; const float* b_m1 = (const float*)d_in[13];
    const float* W_m2  = (const float*)d_in[14]; const float* b_m2 = (const float*)d_in[15];
    const float* W_qkv = (const float*)d_in[16]; const float* b_qkv= (const float*)d_in[17];
    const float* W_ao  = (const float*)d_in[18]; const float* b_ao = (const float*)d_in[19];
    const float* W_g   = (const float*)d_in[20]; const float* b_g  = (const float*)d_in[21];
    const float* W_o   = (const float*)d_in[22]; const float* b_o  = (const float*)d_in[23];
    float* out = (float*)d_out;

    float *p_comb, *p_hid, *p_upd, *p_qkv, *p_att, *p_t1, *p_t2, *p_mix;
    cudaGetSymbolAddress((void**)&p_comb, g_comb);
    cudaGetSymbolAddress((void**)&p_hid,  g_hid);
    cudaGetSymbolAddress((void**)&p_upd,  g_upd);
    cudaGetSymbolAddress((void**)&p_qkv,  g_qkv);
    cudaGetSymbolAddress((void**)&p_att,  g_att);
    cudaGetSymbolAddress((void**)&p_t1,   g_t1);
    cudaGetSymbolAddress((void**)&p_t2,   g_t2);
    cudaGetSymbolAddress((void**)&p_mix,  g_mix);

    zero_hist_kernel<<<16, 256>>>();
    hist_kernel<<<512, 256>>>(ei);
    edge_fused_kernel<<<512, 256>>>(ev, el, W_r1, b_r1, W_r2, b_r2);
    scan_kernel<<<1, 1024>>>();
    scatter_kernel<<<512, 256>>>(ei);
    aggregate_kernel<<<NA, 128>>>();
    embed_kernel<<<NA * 128 / 256, 256>>>(an, emb, b_tp);
    agg_gemm_mma<<<dim3(NA / 64, 4), 128>>>(W_tp);
    gemm_tf32_kernel<<<dim3(NA / 64, 2), 128>>>(p_comb, W_m1, b_m1, p_hid, NA, 128, 128, 128, 1);
    gemm_tf32_kernel<<<dim3(NA / 64, 2), 128>>>(p_hid, W_m2, b_m2, p_upd, NA, 128, 128, 128, 0);
    gemm_tf32_kernel<<<dim3(NA / 64, 6), 128>>>(p_upd, W_qkv, b_qkv, p_qkv, NA, 384, 128, 384, 0);
    attn_part_mma<<<dim3(NA / 64, 4, SPLIT), 128>>>();
    attn_combine_kernel<<<NA * 128 / 256, 256>>>();
    gemm_tf32_kernel<<<dim3(NA / 64, 2), 128>>>(p_att, W_ao, b_ao, p_t1, NA, 128, 128, 128, 0);
    gemm_tf32_kernel<<<dim3(NA / 64, 2), 128>>>(p_upd, W_g, b_g, p_t2, NA, 128, 128, 128, 2);
    mix_kernel<<<NA * 128 / 256, 256>>>();
    gemm_tf32_kernel<<<dim3(NA / 64, 2), 128>>>(p_mix, W_o, b_o, out, NA, 128, 128, 128, 0);
}

// round 9
// speedup vs baseline: 1.0340x; 1.0340x over previous
#include <cuda_runtime.h>
#include <math.h>
#include <stdint.h>

#define NA   4096
#define NE   131072
#define TPIN 1152
#define SPLIT 4

typedef unsigned long long u64t;

__device__ __forceinline__ u64t pk2(float a, float b) {
    u64t r; asm("mov.b64 %0,{%1,%2};" : "=l"(r) : "f"(a), "f"(b)); return r;
}
__device__ __forceinline__ void upk2(u64t v, float& a, float& b) {
    asm("mov.b64 {%0,%1},%2;" : "=f"(a), "=f"(b) : "l"(v));
}
__device__ __forceinline__ u64t ffma2(u64t a, u64t b, u64t c) {
    u64t d; asm("fma.rn.f32x2 %0,%1,%2,%3;" : "=l"(d) : "l"(a), "l"(b), "l"(c)); return d;
}
__device__ __forceinline__ uint32_t tf32r(float f) {
    uint32_t u; asm("cvt.rna.tf32.f32 %0,%1;" : "=r"(u) : "f"(f)); return u;
}
__device__ __forceinline__ void mma_tf32(float* c, const uint32_t* a, uint32_t b0, uint32_t b1) {
    asm volatile("mma.sync.aligned.m16n8k8.row.col.f32.tf32.tf32.f32 "
        "{%0,%1,%2,%3},{%4,%5,%6,%7},{%8,%9},{%0,%1,%2,%3};"
        : "+f"(c[0]), "+f"(c[1]), "+f"(c[2]), "+f"(c[3])
        : "r"(a[0]), "r"(a[1]), "r"(a[2]), "r"(a[3]), "r"(b0), "r"(b1));
}

// ---------------- scratch ----------------
__device__ float g_sh[NE * 9];
__device__ float g_rad[(size_t)NE * 128];
__device__ int   g_hist[NA];
__device__ int   g_off[NA];
__device__ int   g_cur[NA];
__device__ int   g_elist[NE];
__device__ float g_A[(size_t)NA * TPIN];
__device__ float g_comb[NA * 128];
__device__ float g_hid[NA * 128];
__device__ float g_upd[NA * 128];
__device__ float g_qkv[NA * 384];
__device__ float g_att[NA * 128];
__device__ float g_mix[NA * 128];
__device__ float g_pO[(size_t)SPLIT * NA * 128];
__device__ float g_pml[(size_t)SPLIT * NA * 4 * 2];

// ---------------- fused edge kernel ----------------
__global__ __launch_bounds__(256) void edge_fused_kernel(
        const float* __restrict__ ev, const float* __restrict__ el,
        const float* __restrict__ W1, const float* __restrict__ b1,
        const float* __restrict__ W2, const float* __restrict__ b2) {
    __shared__ float sW1[8 * 64];
    __shared__ float sb1[64];
    __shared__ __align__(16) float sW2[64 * 128];
    __shared__ float sb2[128];
    for (int i = threadIdx.x; i < 512;  i += 256) sW1[i] = W1[i];
    for (int i = threadIdx.x; i < 64;   i += 256) sb1[i] = b1[i];
    for (int i = threadIdx.x; i < 8192; i += 256) sW2[i] = W2[i];
    for (int i = threadIdx.x; i < 128;  i += 256) sb2[i] = b2[i];
    __syncthreads();

    int warp = threadIdx.x >> 5, lane = threadIdx.x & 31;
    const float PIC = 3.14159265358979323846f / 6.0f;
    for (int it = 0; it < NE / 4096; it++) {
        int e = blockIdx.x * 8 + warp + it * 4096;
        float vx = ev[e * 3 + 0], vy = ev[e * 3 + 1], vz = ev[e * 3 + 2];
        float l = el[e];
        float r = sqrtf(vx * vx + vy * vy + vz * vz) + 1e-8f;
        float x = vx / r, y = vy / r, z = vz / r;
        if (lane < 9) {
            float s;
            switch (lane) {
                case 0: s = 1.f; break;
                case 1: s = y; break;
                case 2: s = z; break;
                case 3: s = x; break;
                case 4: s = 3.f * z * z - 1.f; break;
                case 5: s = x * z; break;
                case 6: s = y * z; break;
                case 7: s = x * y; break;
                default: s = x * x - y * y; break;
            }
            g_sh[e * 9 + lane] = s;
        }
        float env = 0.5f * (__cosf(l * PIC) + 1.f) * (l < 6.0f ? 1.f : 0.f);
        float inv_l_env = env / l;
        float rb[8];
#pragma unroll
        for (int b = 0; b < 8; b++) rb[b] = __sinf(l * (float)(b + 1) * PIC) * inv_l_env;
        float h1a = sb1[lane], h1b = sb1[lane + 32];
#pragma unroll
        for (int b = 0; b < 8; b++) {
            h1a += rb[b] * sW1[b * 64 + lane];
            h1b += rb[b] * sW1[b * 64 + lane + 32];
        }
        h1a = h1a / (1.f + __expf(-h1a));
        h1b = h1b / (1.f + __expf(-h1b));
        u64t acc0 = pk2(sb2[lane * 4 + 0], sb2[lane * 4 + 1]);
        u64t acc1 = pk2(sb2[lane * 4 + 2], sb2[lane * 4 + 3]);
#pragma unroll
        for (int k = 0; k < 64; k++) {
            float hk = (k < 32) ? __shfl_sync(0xffffffffu, h1a, k)
                                : __shfl_sync(0xffffffffu, h1b, k - 32);
            u64t hk2 = pk2(hk, hk);
            ulonglong2 w = *(const ulonglong2*)&sW2[k * 128 + lane * 4];
            acc0 = ffma2(hk2, w.x, acc0);
            acc1 = ffma2(hk2, w.y, acc1);
        }
        float o0, o1, o2, o3;
        upk2(acc0, o0, o1); upk2(acc1, o2, o3);
        o0 = o0 / (1.f + __expf(-o0));
        o1 = o1 / (1.f + __expf(-o1));
        o2 = o2 / (1.f + __expf(-o2));
        o3 = o3 / (1.f + __expf(-o3));
        *(float4*)&g_rad[(size_t)e * 128 + lane * 4] = make_float4(o0, o1, o2, o3);
    }
}

// ---------------- generic tiled fp32 GEMM ----------------
__global__ void gemm_kernel(const float* __restrict__ A, const float* __restrict__ W,
                            const float* __restrict__ bias, float* __restrict__ C,
                            int M, int N, int K, int act) {
    __shared__ float As[32 * 65];
    __shared__ float Bs[32 * 64];
    int tx = threadIdx.x & 15, ty = threadIdx.x >> 4;
    int m0 = blockIdx.x * 64, n0 = blockIdx.y * 64;
    float acc[4][4] = {};
    for (int k0 = 0; k0 < K; k0 += 32) {
#pragma unroll
        for (int i = 0; i < 8; i++) {
            int l = threadIdx.x + i * 256;
            int m = l >> 5, k = l & 31;
            As[k * 65 + m] = A[(size_t)(m0 + m) * K + k0 + k];
        }
#pragma unroll
        for (int i = 0; i < 8; i++) {
            int l = threadIdx.x + i * 256;
            int k = l >> 6, n = l & 63;
            Bs[k * 64 + n] = W[(size_t)(k0 + k) * N + n0 + n];
        }
        __syncthreads();
#pragma unroll
        for (int k = 0; k < 32; k++) {
            float a[4], b[4];
#pragma unroll
            for (int i = 0; i < 4; i++) a[i] = As[k * 65 + ty * 4 + i];
#pragma unroll
            for (int j = 0; j < 4; j++) b[j] = Bs[k * 64 + tx * 4 + j];
#pragma unroll
            for (int i = 0; i < 4; i++)
#pragma unroll
                for (int j = 0; j < 4; j++) acc[i][j] += a[i] * b[j];
        }
        __syncthreads();
    }
#pragma unroll
    for (int i = 0; i < 4; i++) {
        int m = m0 + ty * 4 + i;
#pragma unroll
        for (int j = 0; j < 4; j++) {
            int n = n0 + tx * 4 + j;
            float v = acc[i][j] + bias[n];
            if (act == 1) v = v / (1.f + __expf(-v));
            else if (act == 2) v = 1.f / (1.f + __expf(-v));
            C[(size_t)m * N + n] = v;
        }
    }
}

// ---------------- CSR build ----------------
__global__ void zero_hist_kernel() {
    int i = blockIdx.x * blockDim.x + threadIdx.x;
    if (i < NA) g_hist[i] = 0;
}
__global__ void hist_kernel(const int* __restrict__ ei) {
    for (int e = blockIdx.x * blockDim.x + threadIdx.x; e < NE; e += gridDim.x * blockDim.x)
        atomicAdd(&g_hist[ei[NE + e]], 1);
}
__global__ void scan_kernel() {
    __shared__ int s[1024];
    int t = threadIdx.x;
    int v0 = g_hist[t * 4], v1 = g_hist[t * 4 + 1], v2 = g_hist[t * 4 + 2], v3 = g_hist[t * 4 + 3];
    int sum = v0 + v1 + v2 + v3;
    s[t] = sum;
    __syncthreads();
    for (int d = 1; d < 1024; d <<= 1) {
        int add = (t >= d) ? s[t - d] : 0;
        __syncthreads();
        s[t] += add;
        __syncthreads();
    }
    int base = s[t] - sum;
    g_off[t * 4 + 0] = base;                 g_cur[t * 4 + 0] = base;
    g_off[t * 4 + 1] = base + v0;            g_cur[t * 4 + 1] = base + v0;
    g_off[t * 4 + 2] = base + v0 + v1;       g_cur[t * 4 + 2] = base + v0 + v1;
    g_off[t * 4 + 3] = base + v0 + v1 + v2;  g_cur[t * 4 + 3] = base + v0 + v1 + v2;
}
__global__ void scatter_kernel(const int* __restrict__ ei) {
    for (int e = blockIdx.x * blockDim.x + threadIdx.x; e < NE; e += gridDim.x * blockDim.x) {
        int d = ei[NE + e];
        int p = atomicAdd(&g_cur[d], 1);
        g_elist[p] = e;
    }
}

// ---------------- per-node rank-1 aggregation ----------------
__global__ void aggregate_kernel() {
    int n = blockIdx.x;
    int c = threadIdx.x;  // 128
    int start = g_off[n], cnt = g_hist[n];
    __shared__ int   eid[32];
    __shared__ float shs[32 * 9];
    float acc[9] = {};
    for (int base = 0; base < cnt; base += 32) {
        int m = min(32, cnt - base);
        if (c < m) eid[c] = g_elist[start + base + c];
        __syncthreads();
        for (int j = c; j < m * 9; j += 128) shs[j] = g_sh[(size_t)eid[j / 9] * 9 + j % 9];
        __syncthreads();
        for (int i = 0; i < m; i++) {
            float rv = g_rad[(size_t)eid[i] * 128 + c];
#pragma unroll
            for (int s = 0; s < 9; s++) acc[s] += rv * shs[i * 9 + s];
        }
        __syncthreads();
    }
    size_t b = (size_t)n * TPIN;
    g_A[b + c] = acc[0];
#pragma unroll
    for (int s = 1; s < 4; s++) g_A[b + 128 + c * 3 + (s - 1)] = acc[s];
#pragma unroll
    for (int s = 4; s < 9; s++) g_A[b + 512 + c * 5 + (s - 4)] = acc[s];
}

// ---------------- embed + bias*deg init of g_comb ----------------
__global__ void embed_kernel(const int* __restrict__ an, const float* __restrict__ emb,
                             const float* __restrict__ btp) {
    int i = blockIdx.x * blockDim.x + threadIdx.x;
    if (i < NA * 128) {
        int n = i >> 7, j = i & 127;
        g_comb[i] = (j < 64) ? emb[an[n] * 64 + j]
                             : btp[j - 64] * (float)g_hist[n];
    }
}

// ---------------- split-K GEMM: g_A @ W_tp[:, :64] ----------------
__global__ void agg_gemm_kernel(const float* __restrict__ Wtp) {
    __shared__ float As[32 * 65];
    __shared__ float Bs[32 * 64];
    int tx = threadIdx.x & 15, ty = threadIdx.x >> 4;
    int m0 = blockIdx.x * 64;
    int kb = blockIdx.y * 288;
    float acc[4][4] = {};
    for (int k0 = 0; k0 < 288; k0 += 32) {
#pragma unroll
        for (int i = 0; i < 8; i++) {
            int l = threadIdx.x + i * 256;
            int m = l >> 5, k = l & 31;
            As[k * 65 + m] = g_A[(size_t)(m0 + m) * TPIN + kb + k0 + k];
        }
#pragma unroll
        for (int i = 0; i < 8; i++) {
            int l = threadIdx.x + i * 256;
            int k = l >> 6, n = l & 63;
            Bs[k * 64 + n] = Wtp[(kb + k0 + k) * 128 + n];
        }
        __syncthreads();
#pragma unroll
        for (int k = 0; k < 32; k++) {
            float a[4], b[4];
#pragma unroll
            for (int i = 0; i < 4; i++) a[i] = As[k * 65 + ty * 4 + i];
#pragma unroll
            for (int j = 0; j < 4; j++) b[j] = Bs[k * 64 + tx * 4 + j];
#pragma unroll
            for (int i = 0; i < 4; i++)
#pragma unroll
                for (int j = 0; j < 4; j++) acc[i][j] += a[i] * b[j];
        }
        __syncthreads();
    }
#pragma unroll
    for (int i = 0; i < 4; i++) {
        int m = m0 + ty * 4 + i;
#pragma unroll
        for (int j = 0; j < 4; j++) {
            int n = tx * 4 + j;
            atomicAdd(&g_comb[m * 128 + 64 + n], acc[i][j]);
        }
    }
}

// ---------------- tensor-core split-KV attention partials ----------------
#define KS_STR 44
#define VS_STR 40
#define PS_STR 76
__global__ __launch_bounds__(128) void attn_part_mma() {
    __shared__ float Ks[64 * KS_STR];
    __shared__ float Vs[64 * VS_STR];
    __shared__ float Ps[64 * PS_STR];
    int tid = threadIdx.x, lane = tid & 31, w = tid >> 5;
    int h = blockIdx.y, sp = blockIdx.z;
    int q0 = blockIdx.x * 64;
    int g = lane >> 2, tg = lane & 3;
    const float sc = 0.17677669529663687f;  // 1/sqrt(32)
    int r0 = q0 + w * 16 + g;

    uint32_t Qf[4][4];
#pragma unroll
    for (int kt = 0; kt < 4; kt++) {
        int k0 = kt * 8 + tg;
        Qf[kt][0] = tf32r(g_qkv[(size_t)r0 * 384 + h * 32 + k0] * sc);
        Qf[kt][1] = tf32r(g_qkv[(size_t)(r0 + 8) * 384 + h * 32 + k0] * sc);
        Qf[kt][2] = tf32r(g_qkv[(size_t)r0 * 384 + h * 32 + k0 + 4] * sc);
        Qf[kt][3] = tf32r(g_qkv[(size_t)(r0 + 8) * 384 + h * 32 + k0 + 4] * sc);
    }

    float O[4][4] = {};
    float M0 = -1e30f, M1 = -1e30f, L0 = 0.f, L1 = 0.f;

    for (int t0 = sp * (NA / SPLIT); t0 < (sp + 1) * (NA / SPLIT); t0 += 64) {
#pragma unroll
        for (int ii = 0; ii < 4; ii++) {
            int idx = tid + ii * 128;
            int key = idx >> 3, d = (idx & 7) * 4;
            float4 kv = *(const float4*)&g_qkv[(size_t)(t0 + key) * 384 + 128 + h * 32 + d];
            float4 vv = *(const float4*)&g_qkv[(size_t)(t0 + key) * 384 + 256 + h * 32 + d];
            float4 kc, vc;
            kc.x = __uint_as_float(tf32r(kv.x)); kc.y = __uint_as_float(tf32r(kv.y));
            kc.z = __uint_as_float(tf32r(kv.z)); kc.w = __uint_as_float(tf32r(kv.w));
            vc.x = __uint_as_float(tf32r(vv.x)); vc.y = __uint_as_float(tf32r(vv.y));
            vc.z = __uint_as_float(tf32r(vv.z)); vc.w = __uint_as_float(tf32r(vv.w));
            *(float4*)&Ks[key * KS_STR + d] = kc;
            *(float4*)&Vs[key * VS_STR + d] = vc;
        }
        __syncthreads();

        float S[8][4];
#pragma unroll
        for (int nt = 0; nt < 8; nt++) { S[nt][0] = 0.f; S[nt][1] = 0.f; S[nt][2] = 0.f; S[nt][3] = 0.f; }
#pragma unroll
        for (int nt = 0; nt < 8; nt++)
#pragma unroll
            for (int kt = 0; kt < 4; kt++) {
                uint32_t b0 = __float_as_uint(Ks[(nt * 8 + g) * KS_STR + kt * 8 + tg]);
                uint32_t b1 = __float_as_uint(Ks[(nt * 8 + g) * KS_STR + kt * 8 + tg + 4]);
                mma_tf32(S[nt], Qf[kt], b0, b1);
            }

        float rm0 = -1e30f, rm1 = -1e30f;
#pragma unroll
        for (int nt = 0; nt < 8; nt++) {
            rm0 = fmaxf(rm0, fmaxf(S[nt][0], S[nt][1]));
            rm1 = fmaxf(rm1, fmaxf(S[nt][2], S[nt][3]));
        }
        rm0 = fmaxf(rm0, __shfl_xor_sync(0xffffffffu, rm0, 1));
        rm0 = fmaxf(rm0, __shfl_xor_sync(0xffffffffu, rm0, 2));
        rm1 = fmaxf(rm1, __shfl_xor_sync(0xffffffffu, rm1, 1));
        rm1 = fmaxf(rm1, __shfl_xor_sync(0xffffffffu, rm1, 2));
        float Mn0 = fmaxf(M0, rm0), Mn1 = fmaxf(M1, rm1);
        float sc0 = __expf(M0 - Mn0), sc1 = __expf(M1 - Mn1);
        M0 = Mn0; M1 = Mn1;
        float ps0 = 0.f, ps1 = 0.f;
#pragma unroll
        for (int nt = 0; nt < 8; nt++) {
            S[nt][0] = __expf(S[nt][0] - Mn0); ps0 += S[nt][0];
            S[nt][1] = __expf(S[nt][1] - Mn0); ps0 += S[nt][1];
            S[nt][2] = __expf(S[nt][2] - Mn1); ps1 += S[nt][2];
            S[nt][3] = __expf(S[nt][3] - Mn1); ps1 += S[nt][3];
        }
        ps0 += __shfl_xor_sync(0xffffffffu, ps0, 1);
        ps0 += __shfl_xor_sync(0xffffffffu, ps0, 2);
        ps1 += __shfl_xor_sync(0xffffffffu, ps1, 1);
        ps1 += __shfl_xor_sync(0xffffffffu, ps1, 2);
        L0 = L0 * sc0 + ps0;
        L1 = L1 * sc1 + ps1;
#pragma unroll
        for (int nt2 = 0; nt2 < 4; nt2++) {
            O[nt2][0] *= sc0; O[nt2][1] *= sc0;
            O[nt2][2] *= sc1; O[nt2][3] *= sc1;
        }

        int pr = w * 16 + g;
#pragma unroll
        for (int nt = 0; nt < 8; nt++) {
            Ps[pr * PS_STR + nt * 8 + 2 * tg]           = __uint_as_float(tf32r(S[nt][0]));
            Ps[pr * PS_STR + nt * 8 + 2 * tg + 1]       = __uint_as_float(tf32r(S[nt][1]));
            Ps[(pr + 8) * PS_STR + nt * 8 + 2 * tg]     = __uint_as_float(tf32r(S[nt][2]));
            Ps[(pr + 8) * PS_STR + nt * 8 + 2 * tg + 1] = __uint_as_float(tf32r(S[nt][3]));
        }
        __syncwarp();

#pragma unroll
        for (int kt2 = 0; kt2 < 8; kt2++) {
            uint32_t A[4];
            A[0] = __float_as_uint(Ps[pr * PS_STR + kt2 * 8 + tg]);
            A[1] = __float_as_uint(Ps[(pr + 8) * PS_STR + kt2 * 8 + tg]);
            A[2] = __float_as_uint(Ps[pr * PS_STR + kt2 * 8 + tg + 4]);
            A[3] = __float_as_uint(Ps[(pr + 8) * PS_STR + kt2 * 8 + tg + 4]);
#pragma unroll
            for (int nt2 = 0; nt2 < 4; nt2++) {
                uint32_t b0 = __float_as_uint(Vs[(kt2 * 8 + tg) * VS_STR + nt2 * 8 + g]);
                uint32_t b1 = __float_as_uint(Vs[(kt2 * 8 + tg + 4) * VS_STR + nt2 * 8 + g]);
                mma_tf32(O[nt2], A, b0, b1);
            }
        }
        __syncthreads();
    }

    size_t base = (size_t)sp * NA;
#pragma unroll
    for (int nt2 = 0; nt2 < 4; nt2++) {
        int col = h * 32 + nt2 * 8 + 2 * tg;
        g_pO[(base + r0) * 128 + col]           = O[nt2][0];
        g_pO[(base + r0) * 128 + col + 1]       = O[nt2][1];
        g_pO[(base + r0 + 8) * 128 + col]       = O[nt2][2];
        g_pO[(base + r0 + 8) * 128 + col + 1]   = O[nt2][3];
    }
    if (tg == 0) {
        g_pml[((base + r0) * 4 + h) * 2 + 0]     = M0;
        g_pml[((base + r0) * 4 + h) * 2 + 1]     = L0;
        g_pml[((base + r0 + 8) * 4 + h) * 2 + 0] = M1;
        g_pml[((base + r0 + 8) * 4 + h) * 2 + 1] = L1;
    }
}

// ---------------- combine split-KV partials ----------------
__global__ void attn_combine_kernel() {
    int i = blockIdx.x * blockDim.x + threadIdx.x;
    if (i >= NA * 128) return;
    int qi = i >> 7, hd = i & 127, h = hd >> 5;
    float m[SPLIT], l[SPLIT];
    float M = -1e30f;
#pragma unroll
    for (int s = 0; s < SPLIT; s++) {
        size_t base = (size_t)s * NA + qi;
        m[s] = g_pml[(base * 4 + h) * 2 + 0];
        l[s] = g_pml[(base * 4 + h) * 2 + 1];
        M = fmaxf(M, m[s]);
    }
    float L = 0.f, O = 0.f;
#pragma unroll
    for (int s = 0; s < SPLIT; s++) {
        float w = __expf(m[s] - M);
        L += l[s] * w;
        O += g_pO[((size_t)s * NA + qi) * 128 + hd] * w;
    }
    g_att[i] = O / L;
}

// ---------------- fused: t1 = att@Wao+bao; g = sig(upd@Wg+bg); mix ---------
__global__ void gemm_dual_kernel(const float* __restrict__ Wao, const float* __restrict__ bao,
                                 const float* __restrict__ Wg,  const float* __restrict__ bg) {
    __shared__ float As1[32 * 65];
    __shared__ float As2[32 * 65];
    __shared__ float Bs1[32 * 64];
    __shared__ float Bs2[32 * 64];
    int tx = threadIdx.x & 15, ty = threadIdx.x >> 4;
    int m0 = blockIdx.x * 64, n0 = blockIdx.y * 64;
    float acc1[4][4] = {}, acc2[4][4] = {};
    for (int k0 = 0; k0 < 128; k0 += 32) {
#pragma unroll
        for (int i = 0; i < 8; i++) {
            int l = threadIdx.x + i * 256;
            int m = l >> 5, k = l & 31;
            As1[k * 65 + m] = g_att[(size_t)(m0 + m) * 128 + k0 + k];
            As2[k * 65 + m] = g_upd[(size_t)(m0 + m) * 128 + k0 + k];
        }
#pragma unroll
        for (int i = 0; i < 8; i++) {
            int l = threadIdx.x + i * 256;
            int k = l >> 6, n = l & 63;
            Bs1[k * 64 + n] = Wao[(k0 + k) * 128 + n0 + n];
            Bs2[k * 64 + n] = Wg[(k0 + k) * 128 + n0 + n];
        }
        __syncthreads();
#pragma unroll
        for (int k = 0; k < 32; k++) {
            float a1[4], a2[4], b1v[4], b2v[4];
#pragma unroll
            for (int i = 0; i < 4; i++) { a1[i] = As1[k * 65 + ty * 4 + i]; a2[i] = As2[k * 65 + ty * 4 + i]; }
#pragma unroll
            for (int j = 0; j < 4; j++) { b1v[j] = Bs1[k * 64 + tx * 4 + j]; b2v[j] = Bs2[k * 64 + tx * 4 + j]; }
#pragma unroll
            for (int i = 0; i < 4; i++)
#pragma unroll
                for (int j = 0; j < 4; j++) {
                    acc1[i][j] += a1[i] * b1v[j];
                    acc2[i][j] += a2[i] * b2v[j];
                }
        }
        __syncthreads();
    }
#pragma unroll
    for (int i = 0; i < 4; i++) {
        int m = m0 + ty * 4 + i;
#pragma unroll
        for (int j = 0; j < 4; j++) {
            int n = n0 + tx * 4 + j;
            float t1 = acc1[i][j] + bao[n];
            float gg = 1.f / (1.f + __expf(-(acc2[i][j] + bg[n])));
            float u = g_upd[(size_t)m * 128 + n];
            g_mix[(size_t)m * 128 + n] = gg * t1 + (1.f - gg) * u;
        }
    }
}

// ---------------- launch ----------------
extern "C" void kernel_launch(void* const* d_in, const int* in_sizes, int n_in,
                              void* d_out, int out_size) {
    const int*   an    = (const int*)d_in[0];
    const int*   ei    = (const int*)d_in[2];
    const float* ev    = (const float*)d_in[3];
    const float* el    = (const float*)d_in[4];
    const float* emb   = (const float*)d_in[5];
    const float* W_r1  = (const float*)d_in[6];  const float* b_r1 = (const float*)d_in[7];
    const float* W_r2  = (const float*)d_in[8];  const float* b_r2 = (const float*)d_in[9];
    const float* W_tp  = (const float*)d_in[10]; const float* b_tp = (const float*)d_in[11];
    const float* W_m1  = (const float*)d_in[12]; const float* b_m1 = (const float*)d_in[13];
    const float* W_m2  = (const float*)d_in[14]; const float* b_m2 = (const float*)d_in[15];
    const float* W_qkv = (const float*)d_in[16]; const float* b_qkv= (const float*)d_in[17];
    const float* W_ao  = (const float*)d_in[18]; const float* b_ao = (const float*)d_in[19];
    const float* W_g   = (const float*)d_in[20]; const float* b_g  = (const float*)d_in[21];
    const float* W_o   = (const float*)d_in[22]; const float* b_o  = (const float*)d_in[23];
    float* out = (float*)d_out;

    float *p_comb, *p_hid, *p_upd, *p_qkv, *p_mix;
    cudaGetSymbolAddress((void**)&p_comb, g_comb);
    cudaGetSymbolAddress((void**)&p_hid,  g_hid);
    cudaGetSymbolAddress((void**)&p_upd,  g_upd);
    cudaGetSymbolAddress((void**)&p_qkv,  g_qkv);
    cudaGetSymbolAddress((void**)&p_mix,  g_mix);

    // NOTE: launch order chosen so the ncu-profiled slot (4th launch) lands on
    // edge_fused_kernel. edge_fused has no dependency on hist/scan; scatter
    // still runs after scan; aggregate after edge+scatter. Semantics unchanged.
    zero_hist_kernel<<<16, 256>>>();
    hist_kernel<<<512, 256>>>(ei);
    scan_kernel<<<1, 1024>>>();
    edge_fused_kernel<<<512, 256>>>(ev, el, W_r1, b_r1, W_r2, b_r2);
    scatter_kernel<<<512, 256>>>(ei);
    aggregate_kernel<<<NA, 128>>>();
    embed_kernel<<<NA * 128 / 256, 256>>>(an, emb, b_tp);
    agg_gemm_kernel<<<dim3(NA / 64, 4), 256>>>(W_tp);
    gemm_kernel<<<dim3(NA / 64, 2), 256>>>(p_comb, W_m1, b_m1, p_hid, NA, 128, 128, 1);
    gemm_kernel<<<dim3(NA / 64, 2), 256>>>(p_hid, W_m2, b_m2, p_upd, NA, 128, 128, 0);
    gemm_kernel<<<dim3(NA / 64, 6), 256>>>(p_upd, W_qkv, b_qkv, p_qkv, NA, 384, 128, 0);
    attn_part_mma<<<dim3(NA / 64, 4, SPLIT), 128>>>();
    attn_combine_kernel<<<NA * 128 / 256, 256>>>();
    gemm_dual_kernel<<<dim3(NA / 64, 2), 256>>>(W_ao, b_ao, W_g, b_g);
    gemm_kernel<<<dim3(NA / 64, 2), 256>>>(p_mix, W_o, b_o, out, NA, 128, 128, 0);
}

// round 10
// speedup vs baseline: 1.3115x; 1.2683x over previous
#include <cuda_runtime.h>
#include <math.h>
#include <stdint.h>

#define NA   4096
#define NE   131072
#define TPIN 1152
#define SPLIT 4

typedef unsigned long long u64t;

__device__ __forceinline__ u64t pk2(float a, float b) {
    u64t r; asm("mov.b64 %0,{%1,%2};" : "=l"(r) : "f"(a), "f"(b)); return r;
}
__device__ __forceinline__ void upk2(u64t v, float& a, float& b) {
    asm("mov.b64 {%0,%1},%2;" : "=f"(a), "=f"(b) : "l"(v));
}
__device__ __forceinline__ u64t ffma2(u64t a, u64t b, u64t c) {
    u64t d; asm("fma.rn.f32x2 %0,%1,%2,%3;" : "=l"(d) : "l"(a), "l"(b), "l"(c)); return d;
}
__device__ __forceinline__ uint32_t tf32r(float f) {
    uint32_t u; asm("cvt.rna.tf32.f32 %0,%1;" : "=r"(u) : "f"(f)); return u;
}
__device__ __forceinline__ void mma_tf32(float* c, const uint32_t* a, uint32_t b0, uint32_t b1) {
    asm volatile("mma.sync.aligned.m16n8k8.row.col.f32.tf32.tf32.f32 "
        "{%0,%1,%2,%3},{%4,%5,%6,%7},{%8,%9},{%0,%1,%2,%3};"
        : "+f"(c[0]), "+f"(c[1]), "+f"(c[2]), "+f"(c[3])
        : "r"(a[0]), "r"(a[1]), "r"(a[2]), "r"(a[3]), "r"(b0), "r"(b1));
}

// ---------------- scratch ----------------
__device__ float g_sh[NE * 9];
__device__ float g_rad[(size_t)NE * 128];
__device__ int   g_hist[NA];
__device__ int   g_off[NA];
__device__ int   g_cur[NA];
__device__ int   g_elist[NE];
__device__ float g_A[(size_t)NA * TPIN];
__device__ float g_comb[NA * 128];
__device__ float g_hid[NA * 128];
__device__ float g_upd[NA * 128];
__device__ float g_qkv[NA * 384];
__device__ float g_att[NA * 128];
__device__ float g_mix[NA * 128];
__device__ float g_pO[(size_t)SPLIT * NA * 128];
__device__ float g_pml[(size_t)SPLIT * NA * 4 * 2];

// ---------------- fused edge kernel, 4-edge blocked ----------------
// 256 threads (8 warps), grid 512. Warp handles 4 edges per outer iteration;
// the W2 row LDS.128 is amortized across the 4 edges (4x less smem traffic).
__global__ __launch_bounds__(256) void edge_fused_kernel(
        const float* __restrict__ ev, const float* __restrict__ el,
        const float* __restrict__ W1, const float* __restrict__ b1,
        const float* __restrict__ W2, const float* __restrict__ b2) {
    __shared__ float sW1[8 * 64];
    __shared__ float sb1[64];
    __shared__ __align__(16) float sW2[64 * 128];
    __shared__ float sb2[128];
    for (int i = threadIdx.x; i < 512;  i += 256) sW1[i] = W1[i];
    for (int i = threadIdx.x; i < 64;   i += 256) sb1[i] = b1[i];
    for (int i = threadIdx.x; i < 8192; i += 256) sW2[i] = W2[i];
    for (int i = threadIdx.x; i < 128;  i += 256) sb2[i] = b2[i];
    __syncthreads();

    int warp = threadIdx.x >> 5, lane = threadIdx.x & 31;
    const float PIC = 3.14159265358979323846f / 6.0f;
    u64t bias0 = pk2(sb2[lane * 4 + 0], sb2[lane * 4 + 1]);
    u64t bias1 = pk2(sb2[lane * 4 + 2], sb2[lane * 4 + 3]);

    for (int it = 0; it < NE / 16384; it++) {           // 8 outer iterations
        int e0 = it * 16384 + (blockIdx.x * 8 + warp) * 4;
        float h1a[4], h1b[4];
#pragma unroll
        for (int j = 0; j < 4; j++) {
            int e = e0 + j;
            float vx = ev[e * 3 + 0], vy = ev[e * 3 + 1], vz = ev[e * 3 + 2];
            float l = el[e];
            float r = sqrtf(vx * vx + vy * vy + vz * vz) + 1e-8f;
            float x = vx / r, y = vy / r, z = vz / r;
            if (lane < 9) {
                float s;
                switch (lane) {
                    case 0: s = 1.f; break;
                    case 1: s = y; break;
                    case 2: s = z; break;
                    case 3: s = x; break;
                    case 4: s = 3.f * z * z - 1.f; break;
                    case 5: s = x * z; break;
                    case 6: s = y * z; break;
                    case 7: s = x * y; break;
                    default: s = x * x - y * y; break;
                }
                g_sh[e * 9 + lane] = s;
            }
            float env = 0.5f * (__cosf(l * PIC) + 1.f) * (l < 6.0f ? 1.f : 0.f);
            float inv_l_env = env / l;
            float rb[8];
#pragma unroll
            for (int b = 0; b < 8; b++) rb[b] = __sinf(l * (float)(b + 1) * PIC) * inv_l_env;
            float a = sb1[lane], bb = sb1[lane + 32];
#pragma unroll
            for (int b = 0; b < 8; b++) {
                a  += rb[b] * sW1[b * 64 + lane];
                bb += rb[b] * sW1[b * 64 + lane + 32];
            }
            h1a[j] = a / (1.f + __expf(-a));
            h1b[j] = bb / (1.f + __expf(-bb));
        }

        u64t acc[4][2];
#pragma unroll
        for (int j = 0; j < 4; j++) { acc[j][0] = bias0; acc[j][1] = bias1; }

#pragma unroll 8
        for (int k = 0; k < 32; k++) {
            ulonglong2 w = *(const ulonglong2*)&sW2[k * 128 + lane * 4];
#pragma unroll
            for (int j = 0; j < 4; j++) {
                float hk = __shfl_sync(0xffffffffu, h1a[j], k);
                u64t hk2 = pk2(hk, hk);
                acc[j][0] = ffma2(hk2, w.x, acc[j][0]);
                acc[j][1] = ffma2(hk2, w.y, acc[j][1]);
            }
        }
#pragma unroll 8
        for (int k = 0; k < 32; k++) {
            ulonglong2 w = *(const ulonglong2*)&sW2[(k + 32) * 128 + lane * 4];
#pragma unroll
            for (int j = 0; j < 4; j++) {
                float hk = __shfl_sync(0xffffffffu, h1b[j], k);
                u64t hk2 = pk2(hk, hk);
                acc[j][0] = ffma2(hk2, w.x, acc[j][0]);
                acc[j][1] = ffma2(hk2, w.y, acc[j][1]);
            }
        }

#pragma unroll
        for (int j = 0; j < 4; j++) {
            float o0, o1, o2, o3;
            upk2(acc[j][0], o0, o1); upk2(acc[j][1], o2, o3);
            o0 = o0 / (1.f + __expf(-o0));
            o1 = o1 / (1.f + __expf(-o1));
            o2 = o2 / (1.f + __expf(-o2));
            o3 = o3 / (1.f + __expf(-o3));
            *(float4*)&g_rad[(size_t)(e0 + j) * 128 + lane * 4] = make_float4(o0, o1, o2, o3);
        }
    }
}

// ---------------- generic tiled fp32 GEMM ----------------
__global__ void gemm_kernel(const float* __restrict__ A, const float* __restrict__ W,
                            const float* __restrict__ bias, float* __restrict__ C,
                            int M, int N, int K, int act) {
    __shared__ float As[32 * 65];
    __shared__ float Bs[32 * 64];
    int tx = threadIdx.x & 15, ty = threadIdx.x >> 4;
    int m0 = blockIdx.x * 64, n0 = blockIdx.y * 64;
    float acc[4][4] = {};
    for (int k0 = 0; k0 < K; k0 += 32) {
#pragma unroll
        for (int i = 0; i < 8; i++) {
            int l = threadIdx.x + i * 256;
            int m = l >> 5, k = l & 31;
            As[k * 65 + m] = A[(size_t)(m0 + m) * K + k0 + k];
        }
#pragma unroll
        for (int i = 0; i < 8; i++) {
            int l = threadIdx.x + i * 256;
            int k = l >> 6, n = l & 63;
            Bs[k * 64 + n] = W[(size_t)(k0 + k) * N + n0 + n];
        }
        __syncthreads();
#pragma unroll
        for (int k = 0; k < 32; k++) {
            float a[4], b[4];
#pragma unroll
            for (int i = 0; i < 4; i++) a[i] = As[k * 65 + ty * 4 + i];
#pragma unroll
            for (int j = 0; j < 4; j++) b[j] = Bs[k * 64 + tx * 4 + j];
#pragma unroll
            for (int i = 0; i < 4; i++)
#pragma unroll
                for (int j = 0; j < 4; j++) acc[i][j] += a[i] * b[j];
        }
        __syncthreads();
    }
#pragma unroll
    for (int i = 0; i < 4; i++) {
        int m = m0 + ty * 4 + i;
#pragma unroll
        for (int j = 0; j < 4; j++) {
            int n = n0 + tx * 4 + j;
            float v = acc[i][j] + bias[n];
            if (act == 1) v = v / (1.f + __expf(-v));
            else if (act == 2) v = 1.f / (1.f + __expf(-v));
            C[(size_t)m * N + n] = v;
        }
    }
}

// ---------------- CSR build ----------------
__global__ void zero_hist_kernel() {
    int i = blockIdx.x * blockDim.x + threadIdx.x;
    if (i < NA) g_hist[i] = 0;
}
__global__ void hist_kernel(const int* __restrict__ ei) {
    for (int e = blockIdx.x * blockDim.x + threadIdx.x; e < NE; e += gridDim.x * blockDim.x)
        atomicAdd(&g_hist[ei[NE + e]], 1);
}
__global__ void scan_kernel() {
    __shared__ int s[1024];
    int t = threadIdx.x;
    int v0 = g_hist[t * 4], v1 = g_hist[t * 4 + 1], v2 = g_hist[t * 4 + 2], v3 = g_hist[t * 4 + 3];
    int sum = v0 + v1 + v2 + v3;
    s[t] = sum;
    __syncthreads();
    for (int d = 1; d < 1024; d <<= 1) {
        int add = (t >= d) ? s[t - d] : 0;
        __syncthreads();
        s[t] += add;
        __syncthreads();
    }
    int base = s[t] - sum;
    g_off[t * 4 + 0] = base;                 g_cur[t * 4 + 0] = base;
    g_off[t * 4 + 1] = base + v0;            g_cur[t * 4 + 1] = base + v0;
    g_off[t * 4 + 2] = base + v0 + v1;       g_cur[t * 4 + 2] = base + v0 + v1;
    g_off[t * 4 + 3] = base + v0 + v1 + v2;  g_cur[t * 4 + 3] = base + v0 + v1 + v2;
}
__global__ void scatter_kernel(const int* __restrict__ ei) {
    for (int e = blockIdx.x * blockDim.x + threadIdx.x; e < NE; e += gridDim.x * blockDim.x) {
        int d = ei[NE + e];
        int p = atomicAdd(&g_cur[d], 1);
        g_elist[p] = e;
    }
}

// ---------------- per-node rank-1 aggregation ----------------
__global__ void aggregate_kernel() {
    int n = blockIdx.x;
    int c = threadIdx.x;  // 128
    int start = g_off[n], cnt = g_hist[n];
    __shared__ int   eid[32];
    __shared__ float shs[32 * 9];
    float acc[9] = {};
    for (int base = 0; base < cnt; base += 32) {
        int m = min(32, cnt - base);
        if (c < m) eid[c] = g_elist[start + base + c];
        __syncthreads();
        for (int j = c; j < m * 9; j += 128) shs[j] = g_sh[(size_t)eid[j / 9] * 9 + j % 9];
        __syncthreads();
        for (int i = 0; i < m; i++) {
            float rv = g_rad[(size_t)eid[i] * 128 + c];
#pragma unroll
            for (int s = 0; s < 9; s++) acc[s] += rv * shs[i * 9 + s];
        }
        __syncthreads();
    }
    size_t b = (size_t)n * TPIN;
    g_A[b + c] = acc[0];
#pragma unroll
    for (int s = 1; s < 4; s++) g_A[b + 128 + c * 3 + (s - 1)] = acc[s];
#pragma unroll
    for (int s = 4; s < 9; s++) g_A[b + 512 + c * 5 + (s - 4)] = acc[s];
}

// ---------------- embed + bias*deg init of g_comb ----------------
__global__ void embed_kernel(const int* __restrict__ an, const float* __restrict__ emb,
                             const float* __restrict__ btp) {
    int i = blockIdx.x * blockDim.x + threadIdx.x;
    if (i < NA * 128) {
        int n = i >> 7, j = i & 127;
        g_comb[i] = (j < 64) ? emb[an[n] * 64 + j]
                             : btp[j - 64] * (float)g_hist[n];
    }
}

// ---------------- split-K GEMM: g_A @ W_tp[:, :64] ----------------
__global__ void agg_gemm_kernel(const float* __restrict__ Wtp) {
    __shared__ float As[32 * 65];
    __shared__ float Bs[32 * 64];
    int tx = threadIdx.x & 15, ty = threadIdx.x >> 4;
    int m0 = blockIdx.x * 64;
    int kb = blockIdx.y * 288;
    float acc[4][4] = {};
    for (int k0 = 0; k0 < 288; k0 += 32) {
#pragma unroll
        for (int i = 0; i < 8; i++) {
            int l = threadIdx.x + i * 256;
            int m = l >> 5, k = l & 31;
            As[k * 65 + m] = g_A[(size_t)(m0 + m) * TPIN + kb + k0 + k];
        }
#pragma unroll
        for (int i = 0; i < 8; i++) {
            int l = threadIdx.x + i * 256;
            int k = l >> 6, n = l & 63;
            Bs[k * 64 + n] = Wtp[(kb + k0 + k) * 128 + n];
        }
        __syncthreads();
#pragma unroll
        for (int k = 0; k < 32; k++) {
            float a[4], b[4];
#pragma unroll
            for (int i = 0; i < 4; i++) a[i] = As[k * 65 + ty * 4 + i];
#pragma unroll
            for (int j = 0; j < 4; j++) b[j] = Bs[k * 64 + tx * 4 + j];
#pragma unroll
            for (int i = 0; i < 4; i++)
#pragma unroll
                for (int j = 0; j < 4; j++) acc[i][j] += a[i] * b[j];
        }
        __syncthreads();
    }
#pragma unroll
    for (int i = 0; i < 4; i++) {
        int m = m0 + ty * 4 + i;
#pragma unroll
        for (int j = 0; j < 4; j++) {
            int n = tx * 4 + j;
            atomicAdd(&g_comb[m * 128 + 64 + n], acc[i][j]);
        }
    }
}

// ---------------- tensor-core split-KV attention partials ----------------
#define KS_STR 44
#define VS_STR 40
#define PS_STR 76
__global__ __launch_bounds__(128) void attn_part_mma() {
    __shared__ float Ks[64 * KS_STR];
    __shared__ float Vs[64 * VS_STR];
    __shared__ float Ps[64 * PS_STR];
    int tid = threadIdx.x, lane = tid & 31, w = tid >> 5;
    int h = blockIdx.y, sp = blockIdx.z;
    int q0 = blockIdx.x * 64;
    int g = lane >> 2, tg = lane & 3;
    const float sc = 0.17677669529663687f;  // 1/sqrt(32)
    int r0 = q0 + w * 16 + g;

    uint32_t Qf[4][4];
#pragma unroll
    for (int kt = 0; kt < 4; kt++) {
        int k0 = kt * 8 + tg;
        Qf[kt][0] = tf32r(g_qkv[(size_t)r0 * 384 + h * 32 + k0] * sc);
        Qf[kt][1] = tf32r(g_qkv[(size_t)(r0 + 8) * 384 + h * 32 + k0] * sc);
        Qf[kt][2] = tf32r(g_qkv[(size_t)r0 * 384 + h * 32 + k0 + 4] * sc);
        Qf[kt][3] = tf32r(g_qkv[(size_t)(r0 + 8) * 384 + h * 32 + k0 + 4] * sc);
    }

    float O[4][4] = {};
    float M0 = -1e30f, M1 = -1e30f, L0 = 0.f, L1 = 0.f;

    for (int t0 = sp * (NA / SPLIT); t0 < (sp + 1) * (NA / SPLIT); t0 += 64) {
#pragma unroll
        for (int ii = 0; ii < 4; ii++) {
            int idx = tid + ii * 128;
            int key = idx >> 3, d = (idx & 7) * 4;
            float4 kv = *(const float4*)&g_qkv[(size_t)(t0 + key) * 384 + 128 + h * 32 + d];
            float4 vv = *(const float4*)&g_qkv[(size_t)(t0 + key) * 384 + 256 + h * 32 + d];
            float4 kc, vc;
            kc.x = __uint_as_float(tf32r(kv.x)); kc.y = __uint_as_float(tf32r(kv.y));
            kc.z = __uint_as_float(tf32r(kv.z)); kc.w = __uint_as_float(tf32r(kv.w));
            vc.x = __uint_as_float(tf32r(vv.x)); vc.y = __uint_as_float(tf32r(vv.y));
            vc.z = __uint_as_float(tf32r(vv.z)); vc.w = __uint_as_float(tf32r(vv.w));
            *(float4*)&Ks[key * KS_STR + d] = kc;
            *(float4*)&Vs[key * VS_STR + d] = vc;
        }
        __syncthreads();

        float S[8][4];
#pragma unroll
        for (int nt = 0; nt < 8; nt++) { S[nt][0] = 0.f; S[nt][1] = 0.f; S[nt][2] = 0.f; S[nt][3] = 0.f; }
#pragma unroll
        for (int nt = 0; nt < 8; nt++)
#pragma unroll
            for (int kt = 0; kt < 4; kt++) {
                uint32_t b0 = __float_as_uint(Ks[(nt * 8 + g) * KS_STR + kt * 8 + tg]);
                uint32_t b1 = __float_as_uint(Ks[(nt * 8 + g) * KS_STR + kt * 8 + tg + 4]);
                mma_tf32(S[nt], Qf[kt], b0, b1);
            }

        float rm0 = -1e30f, rm1 = -1e30f;
#pragma unroll
        for (int nt = 0; nt < 8; nt++) {
            rm0 = fmaxf(rm0, fmaxf(S[nt][0], S[nt][1]));
            rm1 = fmaxf(rm1, fmaxf(S[nt][2], S[nt][3]));
        }
        rm0 = fmaxf(rm0, __shfl_xor_sync(0xffffffffu, rm0, 1));
        rm0 = fmaxf(rm0, __shfl_xor_sync(0xffffffffu, rm0, 2));
        rm1 = fmaxf(rm1, __shfl_xor_sync(0xffffffffu, rm1, 1));
        rm1 = fmaxf(rm1, __shfl_xor_sync(0xffffffffu, rm1, 2));
        float Mn0 = fmaxf(M0, rm0), Mn1 = fmaxf(M1, rm1);
        float sc0 = __expf(M0 - Mn0), sc1 = __expf(M1 - Mn1);
        M0 = Mn0; M1 = Mn1;
        float ps0 = 0.f, ps1 = 0.f;
#pragma unroll
        for (int nt = 0; nt < 8; nt++) {
            S[nt][0] = __expf(S[nt][0] - Mn0); ps0 += S[nt][0];
            S[nt][1] = __expf(S[nt][1] - Mn0); ps0 += S[nt][1];
            S[nt][2] = __expf(S[nt][2] - Mn1); ps1 += S[nt][2];
            S[nt][3] = __expf(S[nt][3] - Mn1); ps1 += S[nt][3];
        }
        ps0 += __shfl_xor_sync(0xffffffffu, ps0, 1);
        ps0 += __shfl_xor_sync(0xffffffffu, ps0, 2);
        ps1 += __shfl_xor_sync(0xffffffffu, ps1, 1);
        ps1 += __shfl_xor_sync(0xffffffffu, ps1, 2);
        L0 = L0 * sc0 + ps0;
        L1 = L1 * sc1 + ps1;
#pragma unroll
        for (int nt2 = 0; nt2 < 4; nt2++) {
            O[nt2][0] *= sc0; O[nt2][1] *= sc0;
            O[nt2][2] *= sc1; O[nt2][3] *= sc1;
        }

        int pr = w * 16 + g;
#pragma unroll
        for (int nt = 0; nt < 8; nt++) {
            Ps[pr * PS_STR + nt * 8 + 2 * tg]           = __uint_as_float(tf32r(S[nt][0]));
            Ps[pr * PS_STR + nt * 8 + 2 * tg + 1]       = __uint_as_float(tf32r(S[nt][1]));
            Ps[(pr + 8) * PS_STR + nt * 8 + 2 * tg]     = __uint_as_float(tf32r(S[nt][2]));
            Ps[(pr + 8) * PS_STR + nt * 8 + 2 * tg + 1] = __uint_as_float(tf32r(S[nt][3]));
        }
        __syncwarp();

#pragma unroll
        for (int kt2 = 0; kt2 < 8; kt2++) {
            uint32_t A[4];
            A[0] = __float_as_uint(Ps[pr * PS_STR + kt2 * 8 + tg]);
            A[1] = __float_as_uint(Ps[(pr + 8) * PS_STR + kt2 * 8 + tg]);
            A[2] = __float_as_uint(Ps[pr * PS_STR + kt2 * 8 + tg + 4]);
            A[3] = __float_as_uint(Ps[(pr + 8) * PS_STR + kt2 * 8 + tg + 4]);
#pragma unroll
            for (int nt2 = 0; nt2 < 4; nt2++) {
                uint32_t b0 = __float_as_uint(Vs[(kt2 * 8 + tg) * VS_STR + nt2 * 8 + g]);
                uint32_t b1 = __float_as_uint(Vs[(kt2 * 8 + tg + 4) * VS_STR + nt2 * 8 + g]);
                mma_tf32(O[nt2], A, b0, b1);
            }
        }
        __syncthreads();
    }

    size_t base = (size_t)sp * NA;
#pragma unroll
    for (int nt2 = 0; nt2 < 4; nt2++) {
        int col = h * 32 + nt2 * 8 + 2 * tg;
        g_pO[(base + r0) * 128 + col]           = O[nt2][0];
        g_pO[(base + r0) * 128 + col + 1]       = O[nt2][1];
        g_pO[(base + r0 + 8) * 128 + col]       = O[nt2][2];
        g_pO[(base + r0 + 8) * 128 + col + 1]   = O[nt2][3];
    }
    if (tg == 0) {
        g_pml[((base + r0) * 4 + h) * 2 + 0]     = M0;
        g_pml[((base + r0) * 4 + h) * 2 + 1]     = L0;
        g_pml[((base + r0 + 8) * 4 + h) * 2 + 0] = M1;
        g_pml[((base + r0 + 8) * 4 + h) * 2 + 1] = L1;
    }
}

// ---------------- combine split-KV partials ----------------
__global__ void attn_combine_kernel() {
    int i = blockIdx.x * blockDim.x + threadIdx.x;
    if (i >= NA * 128) return;
    int qi = i >> 7, hd = i & 127, h = hd >> 5;
    float m[SPLIT], l[SPLIT];
    float M = -1e30f;
#pragma unroll
    for (int s = 0; s < SPLIT; s++) {
        size_t base = (size_t)s * NA + qi;
        m[s] = g_pml[(base * 4 + h) * 2 + 0];
        l[s] = g_pml[(base * 4 + h) * 2 + 1];
        M = fmaxf(M, m[s]);
    }
    float L = 0.f, O = 0.f;
#pragma unroll
    for (int s = 0; s < SPLIT; s++) {
        float w = __expf(m[s] - M);
        L += l[s] * w;
        O += g_pO[((size_t)s * NA + qi) * 128 + hd] * w;
    }
    g_att[i] = O / L;
}

// ---------------- fused: t1 = att@Wao+bao; g = sig(upd@Wg+bg); mix ---------
__global__ void gemm_dual_kernel(const float* __restrict__ Wao, const float* __restrict__ bao,
                                 const float* __restrict__ Wg,  const float* __restrict__ bg) {
    __shared__ float As1[32 * 65];
    __shared__ float As2[32 * 65];
    __shared__ float Bs1[32 * 64];
    __shared__ float Bs2[32 * 64];
    int tx = threadIdx.x & 15, ty = threadIdx.x >> 4;
    int m0 = blockIdx.x * 64, n0 = blockIdx.y * 64;
    float acc1[4][4] = {}, acc2[4][4] = {};
    for (int k0 = 0; k0 < 128; k0 += 32) {
#pragma unroll
        for (int i = 0; i < 8; i++) {
            int l = threadIdx.x + i * 256;
            int m = l >> 5, k = l & 31;
            As1[k * 65 + m] = g_att[(size_t)(m0 + m) * 128 + k0 + k];
            As2[k * 65 + m] = g_upd[(size_t)(m0 + m) * 128 + k0 + k];
        }
#pragma unroll
        for (int i = 0; i < 8; i++) {
            int l = threadIdx.x + i * 256;
            int k = l >> 6, n = l & 63;
            Bs1[k * 64 + n] = Wao[(k0 + k) * 128 + n0 + n];
            Bs2[k * 64 + n] = Wg[(k0 + k) * 128 + n0 + n];
        }
        __syncthreads();
#pragma unroll
        for (int k = 0; k < 32; k++) {
            float a1[4], a2[4], b1v[4], b2v[4];
#pragma unroll
            for (int i = 0; i < 4; i++) { a1[i] = As1[k * 65 + ty * 4 + i]; a2[i] = As2[k * 65 + ty * 4 + i]; }
#pragma unroll
            for (int j = 0; j < 4; j++) { b1v[j] = Bs1[k * 64 + tx * 4 + j]; b2v[j] = Bs2[k * 64 + tx * 4 + j]; }
#pragma unroll
            for (int i = 0; i < 4; i++)
#pragma unroll
                for (int j = 0; j < 4; j++) {
                    acc1[i][j] += a1[i] * b1v[j];
                    acc2[i][j] += a2[i] * b2v[j];
                }
        }
        __syncthreads();
    }
#pragma unroll
    for (int i = 0; i < 4; i++) {
        int m = m0 + ty * 4 + i;
#pragma unroll
        for (int j = 0; j < 4; j++) {
            int n = n0 + tx * 4 + j;
            float t1 = acc1[i][j] + bao[n];
            float gg = 1.f / (1.f + __expf(-(acc2[i][j] + bg[n])));
            float u = g_upd[(size_t)m * 128 + n];
            g_mix[(size_t)m * 128 + n] = gg * t1 + (1.f - gg) * u;
        }
    }
}

// ---------------- launch ----------------
extern "C" void kernel_launch(void* const* d_in, const int* in_sizes, int n_in,
                              void* d_out, int out_size) {
    const int*   an    = (const int*)d_in[0];
    const int*   ei    = (const int*)d_in[2];
    const float* ev    = (const float*)d_in[3];
    const float* el    = (const float*)d_in[4];
    const float* emb   = (const float*)d_in[5];
    const float* W_r1  = (const float*)d_in[6];  const float* b_r1 = (const float*)d_in[7];
    const float* W_r2  = (const float*)d_in[8];  const float* b_r2 = (const float*)d_in[9];
    const float* W_tp  = (const float*)d_in[10]; const float* b_tp = (const float*)d_in[11];
    const float* W_m1  = (const float*)d_in[12]; const float* b_m1 = (const float*)d_in[13];
    const float* W_m2  = (const float*)d_in[14]; const float* b_m2 = (const float*)d_in[15];
    const float* W_qkv = (const float*)d_in[16]; const float* b_qkv= (const float*)d_in[17];
    const float* W_ao  = (const float*)d_in[18]; const float* b_ao = (const float*)d_in[19];
    const float* W_g   = (const float*)d_in[20]; const float* b_g  = (const float*)d_in[21];
    const float* W_o   = (const float*)d_in[22]; const float* b_o  = (const float*)d_in[23];
    float* out = (float*)d_out;

    float *p_comb, *p_hid, *p_upd, *p_qkv, *p_mix;
    cudaGetSymbolAddress((void**)&p_comb, g_comb);
    cudaGetSymbolAddress((void**)&p_hid,  g_hid);
    cudaGetSymbolAddress((void**)&p_upd,  g_upd);
    cudaGetSymbolAddress((void**)&p_qkv,  g_qkv);
    cudaGetSymbolAddress((void**)&p_mix,  g_mix);

    // edge_fused stays in the profiled 4th slot to verify its delta directly.
    zero_hist_kernel<<<16, 256>>>();
    hist_kernel<<<512, 256>>>(ei);
    scan_kernel<<<1, 1024>>>();
    edge_fused_kernel<<<512, 256>>>(ev, el, W_r1, b_r1, W_r2, b_r2);
    scatter_kernel<<<512, 256>>>(ei);
    aggregate_kernel<<<NA, 128>>>();
    embed_kernel<<<NA * 128 / 256, 256>>>(an, emb, b_tp);
    agg_gemm_kernel<<<dim3(NA / 64, 4), 256>>>(W_tp);
    gemm_kernel<<<dim3(NA / 64, 2), 256>>>(p_comb, W_m1, b_m1, p_hid, NA, 128, 128, 1);
    gemm_kernel<<<dim3(NA / 64, 2), 256>>>(p_hid, W_m2, b_m2, p_upd, NA, 128, 128, 0);
    gemm_kernel<<<dim3(NA / 64, 6), 256>>>(p_upd, W_qkv, b_qkv, p_qkv, NA, 384, 128, 0);
    attn_part_mma<<<dim3(NA / 64, 4, SPLIT), 128>>>();
    attn_combine_kernel<<<NA * 128 / 256, 256>>>();
    gemm_dual_kernel<<<dim3(NA / 64, 2), 256>>>(W_ao, b_ao, W_g, b_g);
    gemm_kernel<<<dim3(NA / 64, 2), 256>>>(p_mix, W_o, b_o, out, NA, 128, 128, 0);
}

// round 13
// speedup vs baseline: 1.4142x; 1.0783x over previous
#include <cuda_runtime.h>
#include <math.h>
#include <stdint.h>

#define NA   4096
#define NE   131072
#define TPIN 1152
#define SPLIT 4

__device__ __forceinline__ uint32_t tf32r(float f) {
    uint32_t u; asm("cvt.rna.tf32.f32 %0,%1;" : "=r"(u) : "f"(f)); return u;
}
__device__ __forceinline__ void mma_tf32(float* c, const uint32_t* a, uint32_t b0, uint32_t b1) {
    asm volatile("mma.sync.aligned.m16n8k8.row.col.f32.tf32.tf32.f32 "
        "{%0,%1,%2,%3},{%4,%5,%6,%7},{%8,%9},{%0,%1,%2,%3};"
        : "+f"(c[0]), "+f"(c[1]), "+f"(c[2]), "+f"(c[3])
        : "r"(a[0]), "r"(a[1]), "r"(a[2]), "r"(a[3]), "r"(b0), "r"(b1));
}

// ---------------- scratch ----------------
__device__ float g_sh[NE * 9];
__device__ float g_rad[(size_t)NE * 128];
__device__ int   g_hist[NA];
__device__ int   g_off[NA];
__device__ int   g_cur[NA];
__device__ int   g_elist[NE];
__device__ float g_A[(size_t)NA * TPIN];
__device__ float g_comb[NA * 128];
__device__ float g_hid[NA * 128];
__device__ float g_upd[NA * 128];
__device__ float g_qkv[NA * 384];
__device__ float g_att[NA * 128];
__device__ float g_mix[NA * 128];
__device__ float g_pO[(size_t)SPLIT * NA * 128];
__device__ float g_pml[(size_t)SPLIT * NA * 4 * 2];

// ---------------- fused edge kernel: h1 SIMT + L2 via tf32 MMA -------------
// 256 threads (8 warps), grid 512; block processes 32 edges per iteration.
// Phase 1: each warp computes h1[64] for 4 edges, tf32-rounded into Hs
//          (stride 68: row has 64 cols + pad; 68 % 32 == 4 so A-frag banks
//          (4g+tg) are conflict-free, writes are lane-distinct).
// Phase 2: [32x64] @ [64x128] tf32 MMA + bias + silu -> g_rad.
//          Bs stride 132 (132 % 32 == 4): B-frag banks (4tg+g) distinct.
#define EHS 68
#define EBS 132
__global__ __launch_bounds__(256) void edge_fused_kernel(
        const float* __restrict__ ev, const float* __restrict__ el,
        const float* __restrict__ W1, const float* __restrict__ b1,
        const float* __restrict__ W2, const float* __restrict__ b2) {
    __shared__ float sW1[8 * 64];
    __shared__ float sb1[64];
    __shared__ float sb2[128];
    __shared__ float Bs[64 * EBS];
    __shared__ float Hs[32 * EHS];
    for (int i = threadIdx.x; i < 512;  i += 256) sW1[i] = W1[i];
    for (int i = threadIdx.x; i < 64;   i += 256) sb1[i] = b1[i];
    for (int i = threadIdx.x; i < 128;  i += 256) sb2[i] = b2[i];
    for (int i = threadIdx.x; i < 8192; i += 256) {
        int k = i >> 7, n = i & 127;
        Bs[k * EBS + n] = __uint_as_float(tf32r(W2[k * 128 + n]));
    }
    __syncthreads();

    int tid = threadIdx.x, w = tid >> 5, lane = tid & 31;
    int g = lane >> 2, tg = lane & 3;
    const float PIC = 3.14159265358979323846f / 6.0f;

    for (int it = 0; it < 8; it++) {                 // NE/(512*32) = 8
        int e_base = (it * 512 + blockIdx.x) * 32;

        // ---- phase 1: h1 for 4 edges per warp ----
#pragma unroll
        for (int j = 0; j < 4; j++) {
            int row = w * 4 + j;
            int e = e_base + row;
            float vx = ev[e * 3 + 0], vy = ev[e * 3 + 1], vz = ev[e * 3 + 2];
            float l = el[e];
            float r = sqrtf(vx * vx + vy * vy + vz * vz) + 1e-8f;
            float x = vx / r, y = vy / r, z = vz / r;
            if (lane < 9) {
                float s;
                switch (lane) {
                    case 0: s = 1.f; break;
                    case 1: s = y; break;
                    case 2: s = z; break;
                    case 3: s = x; break;
                    case 4: s = 3.f * z * z - 1.f; break;
                    case 5: s = x * z; break;
                    case 6: s = y * z; break;
                    case 7: s = x * y; break;
                    default: s = x * x - y * y; break;
                }
                g_sh[e * 9 + lane] = s;
            }
            float env = 0.5f * (__cosf(l * PIC) + 1.f) * (l < 6.0f ? 1.f : 0.f);
            float inv_l_env = env / l;
            float rb[8];
#pragma unroll
            for (int b = 0; b < 8; b++) rb[b] = __sinf(l * (float)(b + 1) * PIC) * inv_l_env;
            float a = sb1[lane], bb = sb1[lane + 32];
#pragma unroll
            for (int b = 0; b < 8; b++) {
                a  += rb[b] * sW1[b * 64 + lane];
                bb += rb[b] * sW1[b * 64 + lane + 32];
            }
            a  = a  / (1.f + __expf(-a));
            bb = bb / (1.f + __expf(-bb));
            Hs[row * EHS + lane]      = __uint_as_float(tf32r(a));
            Hs[row * EHS + lane + 32] = __uint_as_float(tf32r(bb));
        }
        __syncthreads();

        // ---- phase 2: [32x64] @ [64x128] tf32 MMA ----
        int mt = w >> 2;                 // m-tile 0..1 (16 rows each)
        int n0 = (w & 3) * 32;           // n-quarter
        float C[4][4] = {};
#pragma unroll
        for (int kt = 0; kt < 8; kt++) {
            uint32_t a[4];
            a[0] = __float_as_uint(Hs[(mt * 16 + g) * EHS + kt * 8 + tg]);
            a[1] = __float_as_uint(Hs[(mt * 16 + g + 8) * EHS + kt * 8 + tg]);
            a[2] = __float_as_uint(Hs[(mt * 16 + g) * EHS + kt * 8 + tg + 4]);
            a[3] = __float_as_uint(Hs[(mt * 16 + g + 8) * EHS + kt * 8 + tg + 4]);
#pragma unroll
            for (int nt = 0; nt < 4; nt++) {
                uint32_t b0 = __float_as_uint(Bs[(kt * 8 + tg) * EBS + n0 + nt * 8 + g]);
                uint32_t b1 = __float_as_uint(Bs[(kt * 8 + tg + 4) * EBS + n0 + nt * 8 + g]);
                mma_tf32(C[nt], a, b0, b1);
            }
        }
        int r0 = e_base + mt * 16 + g, r1 = r0 + 8;
#pragma unroll
        for (int nt = 0; nt < 4; nt++) {
            int col = n0 + nt * 8 + 2 * tg;
            float b0v = sb2[col], b1v = sb2[col + 1];
            float v00 = C[nt][0] + b0v, v01 = C[nt][1] + b1v;
            float v10 = C[nt][2] + b0v, v11 = C[nt][3] + b1v;
            v00 = v00 / (1.f + __expf(-v00)); v01 = v01 / (1.f + __expf(-v01));
            v10 = v10 / (1.f + __expf(-v10)); v11 = v11 / (1.f + __expf(-v11));
            g_rad[(size_t)r0 * 128 + col]     = v00;
            g_rad[(size_t)r0 * 128 + col + 1] = v01;
            g_rad[(size_t)r1 * 128 + col]     = v10;
            g_rad[(size_t)r1 * 128 + col + 1] = v11;
        }
        __syncthreads();
    }
}

// ---------------- generic tiled fp32 GEMM ----------------
__global__ void gemm_kernel(const float* __restrict__ A, const float* __restrict__ W,
                            const float* __restrict__ bias, float* __restrict__ C,
                            int M, int N, int K, int act) {
    __shared__ float As[32 * 65];
    __shared__ float Bs[32 * 64];
    int tx = threadIdx.x & 15, ty = threadIdx.x >> 4;
    int m0 = blockIdx.x * 64, n0 = blockIdx.y * 64;
    float acc[4][4] = {};
    for (int k0 = 0; k0 < K; k0 += 32) {
#pragma unroll
        for (int i = 0; i < 8; i++) {
            int l = threadIdx.x + i * 256;
            int m = l >> 5, k = l & 31;
            As[k * 65 + m] = A[(size_t)(m0 + m) * K + k0 + k];
        }
#pragma unroll
        for (int i = 0; i < 8; i++) {
            int l = threadIdx.x + i * 256;
            int k = l >> 6, n = l & 63;
            Bs[k * 64 + n] = W[(size_t)(k0 + k) * N + n0 + n];
        }
        __syncthreads();
#pragma unroll
        for (int k = 0; k < 32; k++) {
            float a[4], b[4];
#pragma unroll
            for (int i = 0; i < 4; i++) a[i] = As[k * 65 + ty * 4 + i];
#pragma unroll
            for (int j = 0; j < 4; j++) b[j] = Bs[k * 64 + tx * 4 + j];
#pragma unroll
            for (int i = 0; i < 4; i++)
#pragma unroll
                for (int j = 0; j < 4; j++) acc[i][j] += a[i] * b[j];
        }
        __syncthreads();
    }
#pragma unroll
    for (int i = 0; i < 4; i++) {
        int m = m0 + ty * 4 + i;
#pragma unroll
        for (int j = 0; j < 4; j++) {
            int n = n0 + tx * 4 + j;
            float v = acc[i][j] + bias[n];
            if (act == 1) v = v / (1.f + __expf(-v));
            else if (act == 2) v = 1.f / (1.f + __expf(-v));
            C[(size_t)m * N + n] = v;
        }
    }
}

// ---------------- CSR build ----------------
__global__ void zero_hist_kernel() {
    int i = blockIdx.x * blockDim.x + threadIdx.x;
    if (i < NA) g_hist[i] = 0;
}
__global__ void hist_kernel(const int* __restrict__ ei) {
    for (int e = blockIdx.x * blockDim.x + threadIdx.x; e < NE; e += gridDim.x * blockDim.x)
        atomicAdd(&g_hist[ei[NE + e]], 1);
}
__global__ void scan_kernel() {
    __shared__ int s[1024];
    int t = threadIdx.x;
    int v0 = g_hist[t * 4], v1 = g_hist[t * 4 + 1], v2 = g_hist[t * 4 + 2], v3 = g_hist[t * 4 + 3];
    int sum = v0 + v1 + v2 + v3;
    s[t] = sum;
    __syncthreads();
    for (int d = 1; d < 1024; d <<= 1) {
        int add = (t >= d) ? s[t - d] : 0;
        __syncthreads();
        s[t] += add;
        __syncthreads();
    }
    int base = s[t] - sum;
    g_off[t * 4 + 0] = base;                 g_cur[t * 4 + 0] = base;
    g_off[t * 4 + 1] = base + v0;            g_cur[t * 4 + 1] = base + v0;
    g_off[t * 4 + 2] = base + v0 + v1;       g_cur[t * 4 + 2] = base + v0 + v1;
    g_off[t * 4 + 3] = base + v0 + v1 + v2;  g_cur[t * 4 + 3] = base + v0 + v1 + v2;
}
__global__ void scatter_kernel(const int* __restrict__ ei) {
    for (int e = blockIdx.x * blockDim.x + threadIdx.x; e < NE; e += gridDim.x * blockDim.x) {
        int d = ei[NE + e];
        int p = atomicAdd(&g_cur[d], 1);
        g_elist[p] = e;
    }
}

// ---------------- per-node rank-1 aggregation ----------------
__global__ void aggregate_kernel() {
    int n = blockIdx.x;
    int c = threadIdx.x;  // 128
    int start = g_off[n], cnt = g_hist[n];
    __shared__ int   eid[32];
    __shared__ float shs[32 * 9];
    float acc[9] = {};
    for (int base = 0; base < cnt; base += 32) {
        int m = min(32, cnt - base);
        if (c < m) eid[c] = g_elist[start + base + c];
        __syncthreads();
        for (int j = c; j < m * 9; j += 128) shs[j] = g_sh[(size_t)eid[j / 9] * 9 + j % 9];
        __syncthreads();
        for (int i = 0; i < m; i++) {
            float rv = g_rad[(size_t)eid[i] * 128 + c];
#pragma unroll
            for (int s = 0; s < 9; s++) acc[s] += rv * shs[i * 9 + s];
        }
        __syncthreads();
    }
    size_t b = (size_t)n * TPIN;
    g_A[b + c] = acc[0];
#pragma unroll
    for (int s = 1; s < 4; s++) g_A[b + 128 + c * 3 + (s - 1)] = acc[s];
#pragma unroll
    for (int s = 4; s < 9; s++) g_A[b + 512 + c * 5 + (s - 4)] = acc[s];
}

// ---------------- embed + bias*deg init of g_comb ----------------
__global__ void embed_kernel(const int* __restrict__ an, const float* __restrict__ emb,
                             const float* __restrict__ btp) {
    int i = blockIdx.x * blockDim.x + threadIdx.x;
    if (i < NA * 128) {
        int n = i >> 7, j = i & 127;
        g_comb[i] = (j < 64) ? emb[an[n] * 64 + j]
                             : btp[j - 64] * (float)g_hist[n];
    }
}

// ---------------- split-K GEMM: g_A @ W_tp[:, :64] ----------------
__global__ void agg_gemm_kernel(const float* __restrict__ Wtp) {
    __shared__ float As[32 * 65];
    __shared__ float Bs[32 * 64];
    int tx = threadIdx.x & 15, ty = threadIdx.x >> 4;
    int m0 = blockIdx.x * 64;
    int kb = blockIdx.y * 288;
    float acc[4][4] = {};
    for (int k0 = 0; k0 < 288; k0 += 32) {
#pragma unroll
        for (int i = 0; i < 8; i++) {
            int l = threadIdx.x + i * 256;
            int m = l >> 5, k = l & 31;
            As[k * 65 + m] = g_A[(size_t)(m0 + m) * TPIN + kb + k0 + k];
        }
#pragma unroll
        for (int i = 0; i < 8; i++) {
            int l = threadIdx.x + i * 256;
            int k = l >> 6, n = l & 63;
            Bs[k * 64 + n] = Wtp[(kb + k0 + k) * 128 + n];
        }
        __syncthreads();
#pragma unroll
        for (int k = 0; k < 32; k++) {
            float a[4], b[4];
#pragma unroll
            for (int i = 0; i < 4; i++) a[i] = As[k * 65 + ty * 4 + i];
#pragma unroll
            for (int j = 0; j < 4; j++) b[j] = Bs[k * 64 + tx * 4 + j];
#pragma unroll
            for (int i = 0; i < 4; i++)
#pragma unroll
                for (int j = 0; j < 4; j++) acc[i][j] += a[i] * b[j];
        }
        __syncthreads();
    }
#pragma unroll
    for (int i = 0; i < 4; i++) {
        int m = m0 + ty * 4 + i;
#pragma unroll
        for (int j = 0; j < 4; j++) {
            int n = tx * 4 + j;
            atomicAdd(&g_comb[m * 128 + 64 + n], acc[i][j]);
        }
    }
}

// ---------------- tensor-core split-KV attention partials ----------------
#define KS_STR 44
#define VS_STR 40
#define PS_STR 76
__global__ __launch_bounds__(128) void attn_part_mma() {
    __shared__ float Ks[64 * KS_STR];
    __shared__ float Vs[64 * VS_STR];
    __shared__ float Ps[64 * PS_STR];
    int tid = threadIdx.x, lane = tid & 31, w = tid >> 5;
    int h = blockIdx.y, sp = blockIdx.z;
    int q0 = blockIdx.x * 64;
    int g = lane >> 2, tg = lane & 3;
    const float sc = 0.17677669529663687f;  // 1/sqrt(32)
    int r0 = q0 + w * 16 + g;

    uint32_t Qf[4][4];
#pragma unroll
    for (int kt = 0; kt < 4; kt++) {
        int k0 = kt * 8 + tg;
        Qf[kt][0] = tf32r(g_qkv[(size_t)r0 * 384 + h * 32 + k0] * sc);
        Qf[kt][1] = tf32r(g_qkv[(size_t)(r0 + 8) * 384 + h * 32 + k0] * sc);
        Qf[kt][2] = tf32r(g_qkv[(size_t)r0 * 384 + h * 32 + k0 + 4] * sc);
        Qf[kt][3] = tf32r(g_qkv[(size_t)(r0 + 8) * 384 + h * 32 + k0 + 4] * sc);
    }

    float O[4][4] = {};
    float M0 = -1e30f, M1 = -1e30f, L0 = 0.f, L1 = 0.f;

    for (int t0 = sp * (NA / SPLIT); t0 < (sp + 1) * (NA / SPLIT); t0 += 64) {
#pragma unroll
        for (int ii = 0; ii < 4; ii++) {
            int idx = tid + ii * 128;
            int key = idx >> 3, d = (idx & 7) * 4;
            float4 kv = *(const float4*)&g_qkv[(size_t)(t0 + key) * 384 + 128 + h * 32 + d];
            float4 vv = *(const float4*)&g_qkv[(size_t)(t0 + key) * 384 + 256 + h * 32 + d];
            float4 kc, vc;
            kc.x = __uint_as_float(tf32r(kv.x)); kc.y = __uint_as_float(tf32r(kv.y));
            kc.z = __uint_as_float(tf32r(kv.z)); kc.w = __uint_as_float(tf32r(kv.w));
            vc.x = __uint_as_float(tf32r(vv.x)); vc.y = __uint_as_float(tf32r(vv.y));
            vc.z = __uint_as_float(tf32r(vv.z)); vc.w = __uint_as_float(tf32r(vv.w));
            *(float4*)&Ks[key * KS_STR + d] = kc;
            *(float4*)&Vs[key * VS_STR + d] = vc;
        }
        __syncthreads();

        float S[8][4];
#pragma unroll
        for (int nt = 0; nt < 8; nt++) { S[nt][0] = 0.f; S[nt][1] = 0.f; S[nt][2] = 0.f; S[nt][3] = 0.f; }
#pragma unroll
        for (int nt = 0; nt < 8; nt++)
#pragma unroll
            for (int kt = 0; kt < 4; kt++) {
                uint32_t b0 = __float_as_uint(Ks[(nt * 8 + g) * KS_STR + kt * 8 + tg]);
                uint32_t b1 = __float_as_uint(Ks[(nt * 8 + g) * KS_STR + kt * 8 + tg + 4]);
                mma_tf32(S[nt], Qf[kt], b0, b1);
            }

        float rm0 = -1e30f, rm1 = -1e30f;
#pragma unroll
        for (int nt = 0; nt < 8; nt++) {
            rm0 = fmaxf(rm0, fmaxf(S[nt][0], S[nt][1]));
            rm1 = fmaxf(rm1, fmaxf(S[nt][2], S[nt][3]));
        }
        rm0 = fmaxf(rm0, __shfl_xor_sync(0xffffffffu, rm0, 1));
        rm0 = fmaxf(rm0, __shfl_xor_sync(0xffffffffu, rm0, 2));
        rm1 = fmaxf(rm1, __shfl_xor_sync(0xffffffffu, rm1, 1));
        rm1 = fmaxf(rm1, __shfl_xor_sync(0xffffffffu, rm1, 2));
        float Mn0 = fmaxf(M0, rm0), Mn1 = fmaxf(M1, rm1);
        float sc0 = __expf(M0 - Mn0), sc1 = __expf(M1 - Mn1);
        M0 = Mn0; M1 = Mn1;
        float ps0 = 0.f, ps1 = 0.f;
#pragma unroll
        for (int nt = 0; nt < 8; nt++) {
            S[nt][0] = __expf(S[nt][0] - Mn0); ps0 += S[nt][0];
            S[nt][1] = __expf(S[nt][1] - Mn0); ps0 += S[nt][1];
            S[nt][2] = __expf(S[nt][2] - Mn1); ps1 += S[nt][2];
            S[nt][3] = __expf(S[nt][3] - Mn1); ps1 += S[nt][3];
        }
        ps0 += __shfl_xor_sync(0xffffffffu, ps0, 1);
        ps0 += __shfl_xor_sync(0xffffffffu, ps0, 2);
        ps1 += __shfl_xor_sync(0xffffffffu, ps1, 1);
        ps1 += __shfl_xor_sync(0xffffffffu, ps1, 2);
        L0 = L0 * sc0 + ps0;
        L1 = L1 * sc1 + ps1;
#pragma unroll
        for (int nt2 = 0; nt2 < 4; nt2++) {
            O[nt2][0] *= sc0; O[nt2][1] *= sc0;
            O[nt2][2] *= sc1; O[nt2][3] *= sc1;
        }

        int pr = w * 16 + g;
#pragma unroll
        for (int nt = 0; nt < 8; nt++) {
            Ps[pr * PS_STR + nt * 8 + 2 * tg]           = __uint_as_float(tf32r(S[nt][0]));
            Ps[pr * PS_STR + nt * 8 + 2 * tg + 1]       = __uint_as_float(tf32r(S[nt][1]));
            Ps[(pr + 8) * PS_STR + nt * 8 + 2 * tg]     = __uint_as_float(tf32r(S[nt][2]));
            Ps[(pr + 8) * PS_STR + nt * 8 + 2 * tg + 1] = __uint_as_float(tf32r(S[nt][3]));
        }
        __syncwarp();

#pragma unroll
        for (int kt2 = 0; kt2 < 8; kt2++) {
            uint32_t A[4];
            A[0] = __float_as_uint(Ps[pr * PS_STR + kt2 * 8 + tg]);
            A[1] = __float_as_uint(Ps[(pr + 8) * PS_STR + kt2 * 8 + tg]);
            A[2] = __float_as_uint(Ps[pr * PS_STR + kt2 * 8 + tg + 4]);
            A[3] = __float_as_uint(Ps[(pr + 8) * PS_STR + kt2 * 8 + tg + 4]);
#pragma unroll
            for (int nt2 = 0; nt2 < 4; nt2++) {
                uint32_t b0 = __float_as_uint(Vs[(kt2 * 8 + tg) * VS_STR + nt2 * 8 + g]);
                uint32_t b1 = __float_as_uint(Vs[(kt2 * 8 + tg + 4) * VS_STR + nt2 * 8 + g]);
                mma_tf32(O[nt2], A, b0, b1);
            }
        }
        __syncthreads();
    }

    size_t base = (size_t)sp * NA;
#pragma unroll
    for (int nt2 = 0; nt2 < 4; nt2++) {
        int col = h * 32 + nt2 * 8 + 2 * tg;
        g_pO[(base + r0) * 128 + col]           = O[nt2][0];
        g_pO[(base + r0) * 128 + col + 1]       = O[nt2][1];
        g_pO[(base + r0 + 8) * 128 + col]       = O[nt2][2];
        g_pO[(base + r0 + 8) * 128 + col + 1]   = O[nt2][3];
    }
    if (tg == 0) {
        g_pml[((base + r0) * 4 + h) * 2 + 0]     = M0;
        g_pml[((base + r0) * 4 + h) * 2 + 1]     = L0;
        g_pml[((base + r0 + 8) * 4 + h) * 2 + 0] = M1;
        g_pml[((base + r0 + 8) * 4 + h) * 2 + 1] = L1;
    }
}

// ---------------- combine split-KV partials ----------------
__global__ void attn_combine_kernel() {
    int i = blockIdx.x * blockDim.x + threadIdx.x;
    if (i >= NA * 128) return;
    int qi = i >> 7, hd = i & 127, h = hd >> 5;
    float m[SPLIT], l[SPLIT];
    float M = -1e30f;
#pragma unroll
    for (int s = 0; s < SPLIT; s++) {
        size_t base = (size_t)s * NA + qi;
        m[s] = g_pml[(base * 4 + h) * 2 + 0];
        l[s] = g_pml[(base * 4 + h) * 2 + 1];
        M = fmaxf(M, m[s]);
    }
    float L = 0.f, O = 0.f;
#pragma unroll
    for (int s = 0; s < SPLIT; s++) {
        float w = __expf(m[s] - M);
        L += l[s] * w;
        O += g_pO[((size_t)s * NA + qi) * 128 + hd] * w;
    }
    g_att[i] = O / L;
}

// ---------------- fused: t1 = att@Wao+bao; g = sig(upd@Wg+bg); mix ---------
__global__ void gemm_dual_kernel(const float* __restrict__ Wao, const float* __restrict__ bao,
                                 const float* __restrict__ Wg,  const float* __restrict__ bg) {
    __shared__ float As1[32 * 65];
    __shared__ float As2[32 * 65];
    __shared__ float Bs1[32 * 64];
    __shared__ float Bs2[32 * 64];
    int tx = threadIdx.x & 15, ty = threadIdx.x >> 4;
    int m0 = blockIdx.x * 64, n0 = blockIdx.y * 64;
    float acc1[4][4] = {}, acc2[4][4] = {};
    for (int k0 = 0; k0 < 128; k0 += 32) {
#pragma unroll
        for (int i = 0; i < 8; i++) {
            int l = threadIdx.x + i * 256;
            int m = l >> 5, k = l & 31;
            As1[k * 65 + m] = g_att[(size_t)(m0 + m) * 128 + k0 + k];
            As2[k * 65 + m] = g_upd[(size_t)(m0 + m) * 128 + k0 + k];
        }
#pragma unroll
        for (int i = 0; i < 8; i++) {
            int l = threadIdx.x + i * 256;
            int k = l >> 6, n = l & 63;
            Bs1[k * 64 + n] = Wao[(k0 + k) * 128 + n0 + n];
            Bs2[k * 64 + n] = Wg[(k0 + k) * 128 + n0 + n];
        }
        __syncthreads();
#pragma unroll
        for (int k = 0; k < 32; k++) {
            float a1[4], a2[4], b1v[4], b2v[4];
#pragma unroll
            for (int i = 0; i < 4; i++) { a1[i] = As1[k * 65 + ty * 4 + i]; a2[i] = As2[k * 65 + ty * 4 + i]; }
#pragma unroll
            for (int j = 0; j < 4; j++) { b1v[j] = Bs1[k * 64 + tx * 4 + j]; b2v[j] = Bs2[k * 64 + tx * 4 + j]; }
#pragma unroll
            for (int i = 0; i < 4; i++)
#pragma unroll
                for (int j = 0; j < 4; j++) {
                    acc1[i][j] += a1[i] * b1v[j];
                    acc2[i][j] += a2[i] * b2v[j];
                }
        }
        __syncthreads();
    }
#pragma unroll
    for (int i = 0; i < 4; i++) {
        int m = m0 + ty * 4 + i;
#pragma unroll
        for (int j = 0; j < 4; j++) {
            int n = n0 + tx * 4 + j;
            float t1 = acc1[i][j] + bao[n];
            float gg = 1.f / (1.f + __expf(-(acc2[i][j] + bg[n])));
            float u = g_upd[(size_t)m * 128 + n];
            g_mix[(size_t)m * 128 + n] = gg * t1 + (1.f - gg) * u;
        }
    }
}

// ---------------- launch ----------------
extern "C" void kernel_launch(void* const* d_in, const int* in_sizes, int n_in,
                              void* d_out, int out_size) {
    const int*   an    = (const int*)d_in[0];
    const int*   ei    = (const int*)d_in[2];
    const float* ev    = (const float*)d_in[3];
    const float* el    = (const float*)d_in[4];
    const float* emb   = (const float*)d_in[5];
    const float* W_r1  = (const float*)d_in[6];  const float* b_r1 = (const float*)d_in[7];
    const float* W_r2  = (const float*)d_in[8];  const float* b_r2 = (const float*)d_in[9];
    const float* W_tp  = (const float*)d_in[10]; const float* b_tp = (const float*)d_in[11];
    const float* W_m1  = (const float*)d_in[12]; const float* b_m1 = (const float*)d_in[13];
    const float* W_m2  = (const float*)d_in[14]; const float* b_m2 = (const float*)d_in[15];
    const float* W_qkv = (const float*)d_in[16]; const float* b_qkv= (const float*)d_in[17];
    const float* W_ao  = (const float*)d_in[18]; const float* b_ao = (const float*)d_in[19];
    const float* W_g   = (const float*)d_in[20]; const float* b_g  = (const float*)d_in[21];
    const float* W_o   = (const float*)d_in[22]; const float* b_o  = (const float*)d_in[23];
    float* out = (float*)d_out;

    float *p_comb, *p_hid, *p_upd, *p_qkv, *p_mix;
    cudaGetSymbolAddress((void**)&p_comb, g_comb);
    cudaGetSymbolAddress((void**)&p_hid,  g_hid);
    cudaGetSymbolAddress((void**)&p_upd,  g_upd);
    cudaGetSymbolAddress((void**)&p_qkv,  g_qkv);
    cudaGetSymbolAddress((void**)&p_mix,  g_mix);

    // edge_fused stays in the profiled 4th slot to verify its delta directly.
    zero_hist_kernel<<<16, 256>>>();
    hist_kernel<<<512, 256>>>(ei);
    scan_kernel<<<1, 1024>>>();
    edge_fused_kernel<<<512, 256>>>(ev, el, W_r1, b_r1, W_r2, b_r2);
    scatter_kernel<<<512, 256>>>(ei);
    aggregate_kernel<<<NA, 128>>>();
    embed_kernel<<<NA * 128 / 256, 256>>>(an, emb, b_tp);
    agg_gemm_kernel<<<dim3(NA / 64, 4), 256>>>(W_tp);
    gemm_kernel<<<dim3(NA / 64, 2), 256>>>(p_comb, W_m1, b_m1, p_hid, NA, 128, 128, 1);
    gemm_kernel<<<dim3(NA / 64, 2), 256>>>(p_hid, W_m2, b_m2, p_upd, NA, 128, 128, 0);
    gemm_kernel<<<dim3(NA / 64, 6), 256>>>(p_upd, W_qkv, b_qkv, p_qkv, NA, 384, 128, 0);
    attn_part_mma<<<dim3(NA / 64, 4, SPLIT), 128>>>();
    attn_combine_kernel<<<NA * 128 / 256, 256>>>();
    gemm_dual_kernel<<<dim3(NA / 64, 2), 256>>>(W_ao, b_ao, W_g, b_g);
    gemm_kernel<<<dim3(NA / 64, 2), 256>>>(p_mix, W_o, b_o, out, NA, 128, 128, 0);
}